// round 6
// baseline (speedup 1.0000x reference)
#include <cuda_runtime.h>

#define NTOK 4096   // B*L
#define DM   1024
#define DFF  4096
#define SEQ  2048

// ---- scratch (device globals: allocation-free) ----
__device__ float g_q[NTOK * DM];
__device__ float g_k[NTOK * DM];
__device__ float g_v[NTOK * DM];
__device__ float g_ctx[NTOK * DM];
__device__ float g_t0[NTOK * DM];
__device__ float g_x1[NTOK * DM];
__device__ float g_ff[(size_t)NTOK * DFF];

// ---- packed f32x2 helpers (Blackwell FFMA2) ----
__device__ __forceinline__ void ffma2(unsigned long long& d, unsigned long long a, unsigned long long b) {
    asm("fma.rn.f32x2 %0, %1, %2, %0;" : "+l"(d) : "l"(a), "l"(b));
}
__device__ __forceinline__ void unpack2(unsigned long long p, float& lo, float& hi) {
    asm("mov.b64 {%0, %1}, %2;" : "=f"(lo), "=f"(hi) : "l"(p));
}

// =====================================================================
// GEMM: C[M,N] = A[M,K] @ W[K,N] + bias, epilogue: 0=none, 1=GELU, 2=+res
// 128x128 block tile, BK=8, 256 threads, 8x8 per thread via FFMA2.
// A staged duplicated ((a,a) float2) so inner loop needs no pack MOVs.
// =====================================================================
__global__ __launch_bounds__(256, 2)
void gemm_kernel(const float* __restrict__ A, const float* __restrict__ W,
                 const float* __restrict__ bias, const float* __restrict__ res,
                 float* __restrict__ C, int M, int N, int K, int epi)
{
    __shared__ float2 As2[8][128];
    __shared__ float  Bs[8][128];

    const int tid  = threadIdx.x;
    const int tx   = tid & 15;
    const int ty   = tid >> 4;
    const int r0   = ty << 3;
    const int c0   = tx << 3;
    const int brow = blockIdx.y << 7;
    const int bcol = blockIdx.x << 7;

    const int arow = tid >> 1;
    const int acol = (tid & 1) << 2;
    const int bkr  = tid >> 5;
    const int bc   = (tid & 31) << 2;

    const float* Ap = A + (size_t)(brow + arow) * K + acol;
    const float* Wp = W + (size_t)bkr * N + bcol + bc;

    unsigned long long acc[8][4];
#pragma unroll
    for (int i = 0; i < 8; i++)
#pragma unroll
        for (int j = 0; j < 4; j++) acc[i][j] = 0ull;

    float4 afv = *(const float4*)Ap;
    float4 bfv = *(const float4*)Wp;

    for (int k0 = 0; k0 < K; k0 += 8) {
        __syncthreads();
        As2[acol + 0][arow] = make_float2(afv.x, afv.x);
        As2[acol + 1][arow] = make_float2(afv.y, afv.y);
        As2[acol + 2][arow] = make_float2(afv.z, afv.z);
        As2[acol + 3][arow] = make_float2(afv.w, afv.w);
        *(float4*)&Bs[bkr][bc] = bfv;
        __syncthreads();
        if (k0 + 8 < K) {
            afv = *(const float4*)(Ap + k0 + 8);
            bfv = *(const float4*)(Wp + (size_t)(k0 + 8) * N);
        }
#pragma unroll
        for (int kk = 0; kk < 8; kk++) {
            ulonglong2 bv0 = *(const ulonglong2*)&Bs[kk][c0];
            ulonglong2 bv1 = *(const ulonglong2*)&Bs[kk][c0 + 4];
#pragma unroll
            for (int i = 0; i < 8; i++) {
                unsigned long long a2 = *(const unsigned long long*)&As2[kk][r0 + i];
                ffma2(acc[i][0], a2, bv0.x);
                ffma2(acc[i][1], a2, bv0.y);
                ffma2(acc[i][2], a2, bv1.x);
                ffma2(acc[i][3], a2, bv1.y);
            }
        }
    }

    float bvv[8];
#pragma unroll
    for (int j = 0; j < 8; j++) bvv[j] = bias[bcol + c0 + j];

#pragma unroll
    for (int i = 0; i < 8; i++) {
        float ov[8];
        unpack2(acc[i][0], ov[0], ov[1]);
        unpack2(acc[i][1], ov[2], ov[3]);
        unpack2(acc[i][2], ov[4], ov[5]);
        unpack2(acc[i][3], ov[6], ov[7]);
        size_t off = (size_t)(brow + r0 + i) * N + bcol + c0;
#pragma unroll
        for (int j = 0; j < 8; j++) {
            float v = ov[j] + bvv[j];
            if (epi == 1)      v = 0.5f * v * (1.0f + erff(v * 0.70710678118654752f));
            else if (epi == 2) v += res[off + j];
            ov[j] = v;
        }
        *(float4*)&C[off]     = make_float4(ov[0], ov[1], ov[2], ov[3]);
        *(float4*)&C[off + 4] = make_float4(ov[4], ov[5], ov[6], ov[7]);
    }
}

// =====================================================================
// Causal flash attention, fp32. Tile 64 (q) x 64 (kv), Hd=64.
// grid = (32 q-tiles [reversed for load balance], 32 b*h), 256 threads.
// Q,K stored transposed [d][row] (pad 65) in smem; V natural; P^T staged.
// =====================================================================
#define SMEM_ATTN ((3 * 64 * 65 + 64 * 64) * (int)sizeof(float))

__global__ __launch_bounds__(256)
void attn_kernel(const float* __restrict__ Q, const float* __restrict__ K,
                 const float* __restrict__ V, float* __restrict__ ctx)
{
    extern __shared__ float sh[];
    float* sQ = sh;
    float* sK = sh + 64 * 65;
    float* sP = sh + 2 * 64 * 65;
    float* sV = sh + 3 * 64 * 65;

    const int tid = threadIdx.x;
    const int qt  = 31 - blockIdx.x;      // heavy tiles scheduled first
    const int bh  = blockIdx.y;
    const size_t base = (size_t)(bh >> 4) * SEQ * DM + (size_t)(bh & 15) * 64;
    const float* qb = Q + base;
    const float* kb = K + base;
    const float* vb = V + base;

    const int tx = tid & 15, ty = tid >> 4;
    const int r0 = ty << 2, c0 = tx << 2;

#pragma unroll
    for (int it = 0; it < 4; it++) {
        int idx = tid + it * 256;
        int row = idx >> 4;
        int d4  = (idx & 15) << 2;
        float4 t = *(const float4*)(qb + (size_t)(qt * 64 + row) * DM + d4);
        sQ[(d4 + 0) * 65 + row] = t.x * 0.125f;   // fold 1/sqrt(64)
        sQ[(d4 + 1) * 65 + row] = t.y * 0.125f;
        sQ[(d4 + 2) * 65 + row] = t.z * 0.125f;
        sQ[(d4 + 3) * 65 + row] = t.w * 0.125f;
    }

    float o[4][4];
    float m_i[4], l_i[4];
#pragma unroll
    for (int i = 0; i < 4; i++) {
        m_i[i] = -1e30f; l_i[i] = 0.f;
#pragma unroll
        for (int j = 0; j < 4; j++) o[i][j] = 0.f;
    }

    for (int jt = 0; jt <= qt; jt++) {
        __syncthreads();   // prior PV consumption of sK/sV/sP complete
#pragma unroll
        for (int it = 0; it < 4; it++) {
            int idx = tid + it * 256;
            int row = idx >> 4;
            int d4  = (idx & 15) << 2;
            float4 tk = *(const float4*)(kb + (size_t)(jt * 64 + row) * DM + d4);
            sK[(d4 + 0) * 65 + row] = tk.x;
            sK[(d4 + 1) * 65 + row] = tk.y;
            sK[(d4 + 2) * 65 + row] = tk.z;
            sK[(d4 + 3) * 65 + row] = tk.w;
            float4 tv = *(const float4*)(vb + (size_t)(jt * 64 + row) * DM + d4);
            *(float4*)&sV[row * 64 + d4] = tv;
        }
        __syncthreads();

        // S = Q @ K^T  (thread owns rows r0..r0+3, cols c0..c0+3)
        float s[4][4];
#pragma unroll
        for (int i = 0; i < 4; i++)
#pragma unroll
            for (int j = 0; j < 4; j++) s[i][j] = 0.f;

#pragma unroll 8
        for (int d = 0; d < 64; d++) {
            float qf[4], kf[4];
#pragma unroll
            for (int i = 0; i < 4; i++) qf[i] = sQ[d * 65 + r0 + i];
#pragma unroll
            for (int j = 0; j < 4; j++) kf[j] = sK[d * 65 + c0 + j];
#pragma unroll
            for (int i = 0; i < 4; i++)
#pragma unroll
                for (int j = 0; j < 4; j++) s[i][j] += qf[i] * kf[j];
        }

        if (jt == qt) {  // causal mask on diagonal tile
#pragma unroll
            for (int i = 0; i < 4; i++)
#pragma unroll
                for (int j = 0; j < 4; j++)
                    if (c0 + j > r0 + i) s[i][j] = -1e30f;
        }

        // online softmax per row (rows shared across the 16 tx lanes)
#pragma unroll
        for (int i = 0; i < 4; i++) {
            float rm = fmaxf(fmaxf(s[i][0], s[i][1]), fmaxf(s[i][2], s[i][3]));
            rm = fmaxf(rm, __shfl_xor_sync(0xffffffffu, rm, 8, 16));
            rm = fmaxf(rm, __shfl_xor_sync(0xffffffffu, rm, 4, 16));
            rm = fmaxf(rm, __shfl_xor_sync(0xffffffffu, rm, 2, 16));
            rm = fmaxf(rm, __shfl_xor_sync(0xffffffffu, rm, 1, 16));
            float mn    = fmaxf(m_i[i], rm);
            float alpha = __expf(m_i[i] - mn);
            m_i[i] = mn;
            float rs = 0.f;
#pragma unroll
            for (int j = 0; j < 4; j++) {
                float p = __expf(s[i][j] - mn);
                s[i][j] = p;
                rs += p;
            }
            rs += __shfl_xor_sync(0xffffffffu, rs, 8, 16);
            rs += __shfl_xor_sync(0xffffffffu, rs, 4, 16);
            rs += __shfl_xor_sync(0xffffffffu, rs, 2, 16);
            rs += __shfl_xor_sync(0xffffffffu, rs, 1, 16);
            l_i[i] = l_i[i] * alpha + rs;
#pragma unroll
            for (int j = 0; j < 4; j++) o[i][j] *= alpha;
        }

        // stage P^T
#pragma unroll
        for (int i = 0; i < 4; i++)
#pragma unroll
            for (int j = 0; j < 4; j++)
                sP[(c0 + j) * 65 + r0 + i] = s[i][j];
        __syncthreads();

        // O += P @ V  (thread owns rows r0..r0+3, dims c0..c0+3)
#pragma unroll 8
        for (int c = 0; c < 64; c++) {
            float pf[4];
#pragma unroll
            for (int i = 0; i < 4; i++) pf[i] = sP[c * 65 + r0 + i];
            float4 vf = *(const float4*)&sV[c * 64 + c0];
#pragma unroll
            for (int i = 0; i < 4; i++) {
                o[i][0] += pf[i] * vf.x;
                o[i][1] += pf[i] * vf.y;
                o[i][2] += pf[i] * vf.z;
                o[i][3] += pf[i] * vf.w;
            }
        }
    }

#pragma unroll
    for (int i = 0; i < 4; i++) {
        float inv = 1.0f / l_i[i];
        size_t off = base + (size_t)(qt * 64 + r0 + i) * DM + c0;
        *(float4*)&ctx[off] = make_float4(o[i][0] * inv, o[i][1] * inv,
                                          o[i][2] * inv, o[i][3] * inv);
    }
}

// =====================================================================
// LayerNorm: one 256-thread block per 1024-wide row.
// =====================================================================
__global__ __launch_bounds__(256)
void ln_kernel(const float* __restrict__ in, const float* __restrict__ gamma,
               const float* __restrict__ beta, float* __restrict__ out)
{
    __shared__ float rs[8], rs2[8];
    const int row = blockIdx.x;
    const int t = threadIdx.x;
    float4 v = ((const float4*)(in + (size_t)row * DM))[t];
    float s  = v.x + v.y + v.z + v.w;
    float s2 = v.x * v.x + v.y * v.y + v.z * v.z + v.w * v.w;
#pragma unroll
    for (int off = 16; off; off >>= 1) {
        s  += __shfl_xor_sync(0xffffffffu, s, off);
        s2 += __shfl_xor_sync(0xffffffffu, s2, off);
    }
    if ((t & 31) == 0) { rs[t >> 5] = s; rs2[t >> 5] = s2; }
    __syncthreads();
    float ts = 0.f, ts2 = 0.f;
#pragma unroll
    for (int w = 0; w < 8; w++) { ts += rs[w]; ts2 += rs2[w]; }
    float mu   = ts * (1.0f / DM);
    float var  = ts2 * (1.0f / DM) - mu * mu;
    float rstd = rsqrtf(var + 1e-5f);
    float4 g4 = ((const float4*)gamma)[t];
    float4 b4 = ((const float4*)beta)[t];
    float4 o4;
    o4.x = (v.x - mu) * rstd * g4.x + b4.x;
    o4.y = (v.y - mu) * rstd * g4.y + b4.y;
    o4.z = (v.z - mu) * rstd * g4.z + b4.z;
    o4.w = (v.w - mu) * rstd * g4.w + b4.w;
    ((float4*)(out + (size_t)row * DM))[t] = o4;
}

// =====================================================================
extern "C" void kernel_launch(void* const* d_in, const int* in_sizes, int n_in,
                              void* d_out, int out_size)
{
    (void)in_sizes; (void)n_in; (void)out_size;
    const float* x   = (const float*)d_in[0];
    const float* Wq  = (const float*)d_in[1];
    const float* bq  = (const float*)d_in[2];
    const float* Wk  = (const float*)d_in[3];
    const float* bk  = (const float*)d_in[4];
    const float* Wv  = (const float*)d_in[5];
    const float* bv  = (const float*)d_in[6];
    const float* Wo  = (const float*)d_in[7];
    const float* bo  = (const float*)d_in[8];
    const float* W1  = (const float*)d_in[9];
    const float* b1  = (const float*)d_in[10];
    const float* W2  = (const float*)d_in[11];
    const float* b2  = (const float*)d_in[12];
    const float* g1  = (const float*)d_in[13];
    const float* be1 = (const float*)d_in[14];
    const float* g2  = (const float*)d_in[15];
    const float* be2 = (const float*)d_in[16];
    float* out = (float*)d_out;

    float *gq, *gk, *gv, *gctx, *gt0, *gx1, *gff;
    cudaGetSymbolAddress((void**)&gq,   g_q);
    cudaGetSymbolAddress((void**)&gk,   g_k);
    cudaGetSymbolAddress((void**)&gv,   g_v);
    cudaGetSymbolAddress((void**)&gctx, g_ctx);
    cudaGetSymbolAddress((void**)&gt0,  g_t0);
    cudaGetSymbolAddress((void**)&gx1,  g_x1);
    cudaGetSymbolAddress((void**)&gff,  g_ff);

    // Sticky attribute; first (non-captured) correctness call sets it.
    cudaFuncSetAttribute(attn_kernel, cudaFuncAttributeMaxDynamicSharedMemorySize, SMEM_ATTN);

    // QKV projections
    gemm_kernel<<<dim3(DM / 128, NTOK / 128), 256>>>(x, Wq, bq, nullptr, gq, NTOK, DM, DM, 0);
    gemm_kernel<<<dim3(DM / 128, NTOK / 128), 256>>>(x, Wk, bk, nullptr, gk, NTOK, DM, DM, 0);
    gemm_kernel<<<dim3(DM / 128, NTOK / 128), 256>>>(x, Wv, bv, nullptr, gv, NTOK, DM, DM, 0);

    // causal attention
    attn_kernel<<<dim3(SEQ / 64, 32), 256, SMEM_ATTN>>>(gq, gk, gv, gctx);

    // output projection + residual, LN1
    gemm_kernel<<<dim3(DM / 128, NTOK / 128), 256>>>(gctx, Wo, bo, x, gt0, NTOK, DM, DM, 2);
    ln_kernel<<<NTOK, 256>>>(gt0, g1, be1, gx1);

    // FFN: GELU(x1 @ W1 + b1) @ W2 + b2 + x1, LN2 -> out
    gemm_kernel<<<dim3(DFF / 128, NTOK / 128), 256>>>(gx1, W1, b1, nullptr, gff, NTOK, DFF, DM, 1);
    gemm_kernel<<<dim3(DM / 128, NTOK / 128), 256>>>(gff, W2, b2, gx1, gt0, NTOK, DM, DFF, 2);
    ln_kernel<<<NTOK, 256>>>(gt0, g2, be2, out);
}

// round 8
// speedup vs baseline: 2.0035x; 2.0035x over previous
#include <cuda_runtime.h>
#include <cuda_bf16.h>
#include <cstdint>

#define NTOK 4096   // B*L
#define DM   1024
#define DFF  4096
#define SEQ  2048

// ---------------- scratch (device globals: allocation-free) ----------------
__device__ float g_q[NTOK * DM];
__device__ float g_k[NTOK * DM];
__device__ float g_v[NTOK * DM];
__device__ float g_ctx[NTOK * DM];
__device__ float g_t0[NTOK * DM];
__device__ float g_x1[NTOK * DM];
__device__ float g_ff[(size_t)NTOK * DFF];

// bf16 split buffers (hi/lo)
__device__ __nv_bfloat16 g_xh[NTOK * DM],  g_xl[NTOK * DM];
__device__ __nv_bfloat16 g_ctxh[NTOK * DM], g_ctxl[NTOK * DM];
__device__ __nv_bfloat16 g_x1h[NTOK * DM], g_x1l[NTOK * DM];
__device__ __nv_bfloat16 g_ffh[(size_t)NTOK * DFF], g_ffl[(size_t)NTOK * DFF];
// transposed weights [N,K] bf16 hi/lo
__device__ __nv_bfloat16 g_wqh[DM * DM], g_wql[DM * DM];
__device__ __nv_bfloat16 g_wkh[DM * DM], g_wkl[DM * DM];
__device__ __nv_bfloat16 g_wvh[DM * DM], g_wvl[DM * DM];
__device__ __nv_bfloat16 g_woh[DM * DM], g_wol[DM * DM];
__device__ __nv_bfloat16 g_w1h[(size_t)DFF * DM], g_w1l[(size_t)DFF * DM];
__device__ __nv_bfloat16 g_w2h[(size_t)DM * DFF], g_w2l[(size_t)DM * DFF];

// ---------------- PTX helpers (family-portable only; NO tcgen05) ----------------
__device__ __forceinline__ uint32_t smem_u32(const void* p) {
    uint32_t a;
    asm("{ .reg .u64 t; cvta.to.shared.u64 t, %1; cvt.u32.u64 %0, t; }" : "=r"(a) : "l"(p));
    return a;
}
__device__ __forceinline__ void cpasync16(uint32_t dst, const void* src) {
    asm volatile("cp.async.cg.shared.global [%0], [%1], 16;" :: "r"(dst), "l"(src));
}
__device__ __forceinline__ void ldsm4(uint32_t (&r)[4], uint32_t addr) {
    asm volatile("ldmatrix.sync.aligned.m8n8.x4.shared.b16 {%0,%1,%2,%3}, [%4];"
        : "=r"(r[0]), "=r"(r[1]), "=r"(r[2]), "=r"(r[3]) : "r"(addr));
}
__device__ __forceinline__ void mma16816(float (&c)[4], const uint32_t (&a)[4],
                                         uint32_t b0, uint32_t b1) {
    asm volatile("mma.sync.aligned.m16n8k16.row.col.f32.bf16.bf16.f32 "
        "{%0,%1,%2,%3}, {%4,%5,%6,%7}, {%8,%9}, {%0,%1,%2,%3};"
        : "+f"(c[0]), "+f"(c[1]), "+f"(c[2]), "+f"(c[3])
        : "r"(a[0]), "r"(a[1]), "r"(a[2]), "r"(a[3]), "r"(b0), "r"(b1));
}

// =====================================================================
// mma_gemm: C[M,N] = (Ah+Al)[M,K] @ (Bh+Bl)[N,K]^T + bias
// epi: 0=none, 1=GELU(exact), 2=+res
// 128x128 CTA tile, BK=32, 3-stage cp.async pipeline, 8 warps (32m x 64n).
// smem tile rows = 32 bf16 = 64B, swizzle: quad q ^= (row>>1)&3.
// =====================================================================
#define TILEB  8192                   // 128 rows x 64 B
#define STAGEB (4 * TILEB)            // Ah, Al, Bh, Bl
#define SMEM_MMA (3 * STAGEB + 1024)

__device__ __forceinline__ uint32_t swz64(uint32_t off) {
    return off ^ ((off >> 3) & 0x30);
}

__global__ __launch_bounds__(256, 1)
void mma_gemm(const __nv_bfloat16* __restrict__ Ah, const __nv_bfloat16* __restrict__ Al,
              const __nv_bfloat16* __restrict__ Bh, const __nv_bfloat16* __restrict__ Bl,
              const float* __restrict__ bias, const float* __restrict__ res,
              float* __restrict__ C, int M, int N, int K, int epi)
{
    extern __shared__ char smem[];
    const uint32_t s0 = (smem_u32(smem) + 1023) & ~1023u;

    const int tid = threadIdx.x;
    const int wid = tid >> 5, lid = tid & 31;
    const int brow = blockIdx.y << 7, bcol = blockIdx.x << 7;
    const int mw = (wid & 3) << 5;     // warp m offset
    const int nw = (wid >> 2) << 6;    // warp n offset

    // ---- loader mapping: thread -> (row, two 16B quads) ----
    const int lrow = tid >> 1;
    const int q0   = (tid & 1) << 1;
    const uint32_t sw0 = swz64(lrow * 64 + q0 * 16);
    const uint32_t sw1 = swz64(lrow * 64 + q0 * 16 + 16);
    const size_t ga = (size_t)(brow + lrow) * K + q0 * 8;
    const size_t gb = (size_t)(bcol + lrow) * K + q0 * 8;

    const int nchunk = K >> 5;

    auto issue = [&](int c) {
        const uint32_t st = s0 + (uint32_t)(c % 3) * STAGEB;
        const size_t k0 = (size_t)c << 5;
        cpasync16(st + 0 * TILEB + sw0, Ah + ga + k0);
        cpasync16(st + 0 * TILEB + sw1, Ah + ga + k0 + 8);
        cpasync16(st + 1 * TILEB + sw0, Al + ga + k0);
        cpasync16(st + 1 * TILEB + sw1, Al + ga + k0 + 8);
        cpasync16(st + 2 * TILEB + sw0, Bh + gb + k0);
        cpasync16(st + 2 * TILEB + sw1, Bh + gb + k0 + 8);
        cpasync16(st + 3 * TILEB + sw0, Bl + gb + k0);
        cpasync16(st + 3 * TILEB + sw1, Bl + gb + k0 + 8);
    };

    issue(0);
    asm volatile("cp.async.commit_group;");
    issue(1);
    asm volatile("cp.async.commit_group;");

    float acc[2][8][4];
#pragma unroll
    for (int i = 0; i < 2; i++)
#pragma unroll
        for (int j = 0; j < 8; j++)
#pragma unroll
            for (int t = 0; t < 4; t++) acc[i][j][t] = 0.f;

    // ldmatrix per-lane address components
    const int a_row = lid & 15;
    const int a_h   = lid >> 4;
    const int b_row = (lid & 7) + ((lid >> 4) << 3);
    const int b_h   = (lid >> 3) & 1;

    for (int c = 0; c < nchunk; c++) {
        asm volatile("cp.async.wait_group 1;");
        __syncthreads();
        if (c + 2 < nchunk) issue(c + 2);
        asm volatile("cp.async.commit_group;");

        const uint32_t st  = s0 + (uint32_t)(c % 3) * STAGEB;
        const uint32_t sAh = st, sAl = st + TILEB;
        const uint32_t sBh = st + 2 * TILEB, sBl = st + 3 * TILEB;

#pragma unroll
        for (int ks = 0; ks < 2; ks++) {
            uint32_t ah[2][4], al[2][4];
#pragma unroll
            for (int i = 0; i < 2; i++) {
                uint32_t off = swz64((mw + i * 16 + a_row) * 64 + ks * 32 + a_h * 16);
                ldsm4(ah[i], sAh + off);
                ldsm4(al[i], sAl + off);
            }
            uint32_t bh[8][2], bl[8][2];
#pragma unroll
            for (int j = 0; j < 4; j++) {
                uint32_t off = swz64((nw + j * 16 + b_row) * 64 + ks * 32 + b_h * 16);
                uint32_t t0[4], t1[4];
                ldsm4(t0, sBh + off);
                ldsm4(t1, sBl + off);
                bh[2*j][0] = t0[0]; bh[2*j][1] = t0[1]; bh[2*j+1][0] = t0[2]; bh[2*j+1][1] = t0[3];
                bl[2*j][0] = t1[0]; bl[2*j][1] = t1[1]; bl[2*j+1][0] = t1[2]; bl[2*j+1][1] = t1[3];
            }
#pragma unroll
            for (int i = 0; i < 2; i++)
#pragma unroll
                for (int j = 0; j < 8; j++) {
                    mma16816(acc[i][j], ah[i], bh[j][0], bh[j][1]);  // hi*hi
                    mma16816(acc[i][j], ah[i], bl[j][0], bl[j][1]);  // hi*lo
                    mma16816(acc[i][j], al[i], bh[j][0], bh[j][1]);  // lo*hi
                }
        }
    }

    // ---- epilogue ----
    const int erow = lid >> 2;
    const int ecol = (lid & 3) << 1;
#pragma unroll
    for (int i = 0; i < 2; i++)
#pragma unroll
        for (int j = 0; j < 8; j++)
#pragma unroll
            for (int h = 0; h < 2; h++) {
                const int m = brow + mw + i * 16 + erow + h * 8;
                const int n = bcol + nw + j * 8 + ecol;
                float v0 = acc[i][j][h * 2 + 0] + bias[n];
                float v1 = acc[i][j][h * 2 + 1] + bias[n + 1];
                const size_t off = (size_t)m * N + n;
                if (epi == 1) {
                    v0 = 0.5f * v0 * (1.0f + erff(v0 * 0.70710678118654752f));
                    v1 = 0.5f * v1 * (1.0f + erff(v1 * 0.70710678118654752f));
                } else if (epi == 2) {
                    float2 rr = *(const float2*)&res[off];
                    v0 += rr.x; v1 += rr.y;
                }
                *(float2*)&C[off] = make_float2(v0, v1);
            }
}

// =====================================================================
// conversions: fp32 -> bf16 hi/lo split
// =====================================================================
__device__ __forceinline__ void split_bf16(float v, __nv_bfloat16& h, __nv_bfloat16& l) {
    h = __float2bfloat16(v);
    l = __float2bfloat16(v - __bfloat162float(h));
}

__global__ __launch_bounds__(256)
void conv_act(const float* __restrict__ in, __nv_bfloat16* __restrict__ hi,
              __nv_bfloat16* __restrict__ lo)
{
    const size_t i = ((size_t)blockIdx.x * 256 + threadIdx.x) * 4;
    float4 v = *(const float4*)(in + i);
    __nv_bfloat16 h0, h1, h2, h3, l0, l1, l2, l3;
    split_bf16(v.x, h0, l0); split_bf16(v.y, h1, l1);
    split_bf16(v.z, h2, l2); split_bf16(v.w, h3, l3);
    *(__nv_bfloat162*)(hi + i)     = __nv_bfloat162(h0, h1);
    *(__nv_bfloat162*)(hi + i + 2) = __nv_bfloat162(h2, h3);
    *(__nv_bfloat162*)(lo + i)     = __nv_bfloat162(l0, l1);
    *(__nv_bfloat162*)(lo + i + 2) = __nv_bfloat162(l2, l3);
}

// transpose W[K,N] -> hi/lo [N,K]
__global__ __launch_bounds__(256)
void conv_wT(const float* __restrict__ W, __nv_bfloat16* __restrict__ hi,
             __nv_bfloat16* __restrict__ lo, int K, int N)
{
    __shared__ float t[32][33];
    const int n0 = blockIdx.x * 32, k0 = blockIdx.y * 32;
    const int tx = threadIdx.x & 31, ty = threadIdx.x >> 5;  // 32 x 8
#pragma unroll
    for (int j = 0; j < 4; j++)
        t[ty + 8 * j][tx] = W[(size_t)(k0 + ty + 8 * j) * N + n0 + tx];
    __syncthreads();
#pragma unroll
    for (int j = 0; j < 4; j++) {
        float v = t[tx][ty + 8 * j];
        __nv_bfloat16 h, l;
        split_bf16(v, h, l);
        size_t o = (size_t)(n0 + ty + 8 * j) * K + k0 + tx;
        hi[o] = h; lo[o] = l;
    }
}

// =====================================================================
// Causal flash attention, fp32 (unchanged; next round's target).
// =====================================================================
#define SMEM_ATTN ((3 * 64 * 65 + 64 * 64) * (int)sizeof(float))

__global__ __launch_bounds__(256)
void attn_kernel(const float* __restrict__ Q, const float* __restrict__ K,
                 const float* __restrict__ V, float* __restrict__ ctx)
{
    extern __shared__ float sh[];
    float* sQ = sh;
    float* sK = sh + 64 * 65;
    float* sP = sh + 2 * 64 * 65;
    float* sV = sh + 3 * 64 * 65;

    const int tid = threadIdx.x;
    const int qt  = 31 - blockIdx.x;
    const int bh  = blockIdx.y;
    const size_t base = (size_t)(bh >> 4) * SEQ * DM + (size_t)(bh & 15) * 64;
    const float* qb = Q + base;
    const float* kb = K + base;
    const float* vb = V + base;

    const int tx = tid & 15, ty = tid >> 4;
    const int r0 = ty << 2, c0 = tx << 2;

#pragma unroll
    for (int it = 0; it < 4; it++) {
        int idx = tid + it * 256;
        int row = idx >> 4;
        int d4  = (idx & 15) << 2;
        float4 t = *(const float4*)(qb + (size_t)(qt * 64 + row) * DM + d4);
        sQ[(d4 + 0) * 65 + row] = t.x * 0.125f;
        sQ[(d4 + 1) * 65 + row] = t.y * 0.125f;
        sQ[(d4 + 2) * 65 + row] = t.z * 0.125f;
        sQ[(d4 + 3) * 65 + row] = t.w * 0.125f;
    }

    float o[4][4];
    float m_i[4], l_i[4];
#pragma unroll
    for (int i = 0; i < 4; i++) {
        m_i[i] = -1e30f; l_i[i] = 0.f;
#pragma unroll
        for (int j = 0; j < 4; j++) o[i][j] = 0.f;
    }

    for (int jt = 0; jt <= qt; jt++) {
        __syncthreads();
#pragma unroll
        for (int it = 0; it < 4; it++) {
            int idx = tid + it * 256;
            int row = idx >> 4;
            int d4  = (idx & 15) << 2;
            float4 tk = *(const float4*)(kb + (size_t)(jt * 64 + row) * DM + d4);
            sK[(d4 + 0) * 65 + row] = tk.x;
            sK[(d4 + 1) * 65 + row] = tk.y;
            sK[(d4 + 2) * 65 + row] = tk.z;
            sK[(d4 + 3) * 65 + row] = tk.w;
            float4 tv = *(const float4*)(vb + (size_t)(jt * 64 + row) * DM + d4);
            *(float4*)&sV[row * 64 + d4] = tv;
        }
        __syncthreads();

        float s[4][4];
#pragma unroll
        for (int i = 0; i < 4; i++)
#pragma unroll
            for (int j = 0; j < 4; j++) s[i][j] = 0.f;

#pragma unroll 8
        for (int d = 0; d < 64; d++) {
            float qf[4], kf[4];
#pragma unroll
            for (int i = 0; i < 4; i++) qf[i] = sQ[d * 65 + r0 + i];
#pragma unroll
            for (int j = 0; j < 4; j++) kf[j] = sK[d * 65 + c0 + j];
#pragma unroll
            for (int i = 0; i < 4; i++)
#pragma unroll
                for (int j = 0; j < 4; j++) s[i][j] += qf[i] * kf[j];
        }

        if (jt == qt) {
#pragma unroll
            for (int i = 0; i < 4; i++)
#pragma unroll
                for (int j = 0; j < 4; j++)
                    if (c0 + j > r0 + i) s[i][j] = -1e30f;
        }

#pragma unroll
        for (int i = 0; i < 4; i++) {
            float rm = fmaxf(fmaxf(s[i][0], s[i][1]), fmaxf(s[i][2], s[i][3]));
            rm = fmaxf(rm, __shfl_xor_sync(0xffffffffu, rm, 8, 16));
            rm = fmaxf(rm, __shfl_xor_sync(0xffffffffu, rm, 4, 16));
            rm = fmaxf(rm, __shfl_xor_sync(0xffffffffu, rm, 2, 16));
            rm = fmaxf(rm, __shfl_xor_sync(0xffffffffu, rm, 1, 16));
            float mn    = fmaxf(m_i[i], rm);
            float alpha = __expf(m_i[i] - mn);
            m_i[i] = mn;
            float rs = 0.f;
#pragma unroll
            for (int j = 0; j < 4; j++) {
                float p = __expf(s[i][j] - mn);
                s[i][j] = p;
                rs += p;
            }
            rs += __shfl_xor_sync(0xffffffffu, rs, 8, 16);
            rs += __shfl_xor_sync(0xffffffffu, rs, 4, 16);
            rs += __shfl_xor_sync(0xffffffffu, rs, 2, 16);
            rs += __shfl_xor_sync(0xffffffffu, rs, 1, 16);
            l_i[i] = l_i[i] * alpha + rs;
#pragma unroll
            for (int j = 0; j < 4; j++) o[i][j] *= alpha;
        }

#pragma unroll
        for (int i = 0; i < 4; i++)
#pragma unroll
            for (int j = 0; j < 4; j++)
                sP[(c0 + j) * 65 + r0 + i] = s[i][j];
        __syncthreads();

#pragma unroll 8
        for (int c = 0; c < 64; c++) {
            float pf[4];
#pragma unroll
            for (int i = 0; i < 4; i++) pf[i] = sP[c * 65 + r0 + i];
            float4 vf = *(const float4*)&sV[c * 64 + c0];
#pragma unroll
            for (int i = 0; i < 4; i++) {
                o[i][0] += pf[i] * vf.x;
                o[i][1] += pf[i] * vf.y;
                o[i][2] += pf[i] * vf.z;
                o[i][3] += pf[i] * vf.w;
            }
        }
    }

#pragma unroll
    for (int i = 0; i < 4; i++) {
        float inv = 1.0f / l_i[i];
        size_t off = base + (size_t)(qt * 64 + r0 + i) * DM + c0;
        *(float4*)&ctx[off] = make_float4(o[i][0] * inv, o[i][1] * inv,
                                          o[i][2] * inv, o[i][3] * inv);
    }
}

// =====================================================================
// LayerNorm: one 256-thread block per 1024-wide row.
// =====================================================================
__global__ __launch_bounds__(256)
void ln_kernel(const float* __restrict__ in, const float* __restrict__ gamma,
               const float* __restrict__ beta, float* __restrict__ out)
{
    __shared__ float rs[8], rs2[8];
    const int row = blockIdx.x;
    const int t = threadIdx.x;
    float4 v = ((const float4*)(in + (size_t)row * DM))[t];
    float s  = v.x + v.y + v.z + v.w;
    float s2 = v.x * v.x + v.y * v.y + v.z * v.z + v.w * v.w;
#pragma unroll
    for (int off = 16; off; off >>= 1) {
        s  += __shfl_xor_sync(0xffffffffu, s, off);
        s2 += __shfl_xor_sync(0xffffffffu, s2, off);
    }
    if ((t & 31) == 0) { rs[t >> 5] = s; rs2[t >> 5] = s2; }
    __syncthreads();
    float ts = 0.f, ts2 = 0.f;
#pragma unroll
    for (int w = 0; w < 8; w++) { ts += rs[w]; ts2 += rs2[w]; }
    float mu   = ts * (1.0f / DM);
    float var  = ts2 * (1.0f / DM) - mu * mu;
    float rstd = rsqrtf(var + 1e-5f);
    float4 g4 = ((const float4*)gamma)[t];
    float4 b4 = ((const float4*)beta)[t];
    float4 o4;
    o4.x = (v.x - mu) * rstd * g4.x + b4.x;
    o4.y = (v.y - mu) * rstd * g4.y + b4.y;
    o4.z = (v.z - mu) * rstd * g4.z + b4.z;
    o4.w = (v.w - mu) * rstd * g4.w + b4.w;
    ((float4*)(out + (size_t)row * DM))[t] = o4;
}

// =====================================================================
extern "C" void kernel_launch(void* const* d_in, const int* in_sizes, int n_in,
                              void* d_out, int out_size)
{
    (void)in_sizes; (void)n_in; (void)out_size;
    const float* x   = (const float*)d_in[0];
    const float* Wq  = (const float*)d_in[1];
    const float* bq  = (const float*)d_in[2];
    const float* Wk  = (const float*)d_in[3];
    const float* bk  = (const float*)d_in[4];
    const float* Wv  = (const float*)d_in[5];
    const float* bv  = (const float*)d_in[6];
    const float* Wo  = (const float*)d_in[7];
    const float* bo  = (const float*)d_in[8];
    const float* W1  = (const float*)d_in[9];
    const float* b1  = (const float*)d_in[10];
    const float* W2  = (const float*)d_in[11];
    const float* b2  = (const float*)d_in[12];
    const float* g1  = (const float*)d_in[13];
    const float* be1 = (const float*)d_in[14];
    const float* g2  = (const float*)d_in[15];
    const float* be2 = (const float*)d_in[16];
    float* out = (float*)d_out;

    float *gq, *gk, *gv, *gctx, *gt0, *gx1, *gff;
    cudaGetSymbolAddress((void**)&gq,   g_q);
    cudaGetSymbolAddress((void**)&gk,   g_k);
    cudaGetSymbolAddress((void**)&gv,   g_v);
    cudaGetSymbolAddress((void**)&gctx, g_ctx);
    cudaGetSymbolAddress((void**)&gt0,  g_t0);
    cudaGetSymbolAddress((void**)&gx1,  g_x1);
    cudaGetSymbolAddress((void**)&gff,  g_ff);

    __nv_bfloat16 *xh, *xl, *ctxh, *ctxl, *x1h, *x1l, *ffh, *ffl;
    __nv_bfloat16 *wqh, *wql, *wkh, *wkl, *wvh, *wvl, *woh, *wol, *w1h, *w1l, *w2h, *w2l;
    cudaGetSymbolAddress((void**)&xh,   g_xh);   cudaGetSymbolAddress((void**)&xl,   g_xl);
    cudaGetSymbolAddress((void**)&ctxh, g_ctxh); cudaGetSymbolAddress((void**)&ctxl, g_ctxl);
    cudaGetSymbolAddress((void**)&x1h,  g_x1h);  cudaGetSymbolAddress((void**)&x1l,  g_x1l);
    cudaGetSymbolAddress((void**)&ffh,  g_ffh);  cudaGetSymbolAddress((void**)&ffl,  g_ffl);
    cudaGetSymbolAddress((void**)&wqh,  g_wqh);  cudaGetSymbolAddress((void**)&wql,  g_wql);
    cudaGetSymbolAddress((void**)&wkh,  g_wkh);  cudaGetSymbolAddress((void**)&wkl,  g_wkl);
    cudaGetSymbolAddress((void**)&wvh,  g_wvh);  cudaGetSymbolAddress((void**)&wvl,  g_wvl);
    cudaGetSymbolAddress((void**)&woh,  g_woh);  cudaGetSymbolAddress((void**)&wol,  g_wol);
    cudaGetSymbolAddress((void**)&w1h,  g_w1h);  cudaGetSymbolAddress((void**)&w1l,  g_w1l);
    cudaGetSymbolAddress((void**)&w2h,  g_w2h);  cudaGetSymbolAddress((void**)&w2l,  g_w2l);

    cudaFuncSetAttribute(attn_kernel, cudaFuncAttributeMaxDynamicSharedMemorySize, SMEM_ATTN);
    cudaFuncSetAttribute(mma_gemm,   cudaFuncAttributeMaxDynamicSharedMemorySize, SMEM_MMA);

    // ---- weight transpose+split ----
    conv_wT<<<dim3(DM / 32,  DM / 32),  256>>>(Wq, wqh, wql, DM, DM);
    conv_wT<<<dim3(DM / 32,  DM / 32),  256>>>(Wk, wkh, wkl, DM, DM);
    conv_wT<<<dim3(DM / 32,  DM / 32),  256>>>(Wv, wvh, wvl, DM, DM);
    conv_wT<<<dim3(DM / 32,  DM / 32),  256>>>(Wo, woh, wol, DM, DM);
    conv_wT<<<dim3(DFF / 32, DM / 32),  256>>>(W1, w1h, w1l, DM, DFF);
    conv_wT<<<dim3(DM / 32,  DFF / 32), 256>>>(W2, w2h, w2l, DFF, DM);

    // ---- x split ----
    conv_act<<<(NTOK * DM) / 1024, 256>>>(x, xh, xl);

    // ---- QKV ----
    mma_gemm<<<dim3(DM / 128, NTOK / 128), 256, SMEM_MMA>>>(xh, xl, wqh, wql, bq, nullptr, gq, NTOK, DM, DM, 0);
    mma_gemm<<<dim3(DM / 128, NTOK / 128), 256, SMEM_MMA>>>(xh, xl, wkh, wkl, bk, nullptr, gk, NTOK, DM, DM, 0);
    mma_gemm<<<dim3(DM / 128, NTOK / 128), 256, SMEM_MMA>>>(xh, xl, wvh, wvl, bv, nullptr, gv, NTOK, DM, DM, 0);

    // ---- attention ----
    attn_kernel<<<dim3(SEQ / 64, 32), 256, SMEM_ATTN>>>(gq, gk, gv, gctx);
    conv_act<<<(NTOK * DM) / 1024, 256>>>(gctx, ctxh, ctxl);

    // ---- Wo + residual, LN1 ----
    mma_gemm<<<dim3(DM / 128, NTOK / 128), 256, SMEM_MMA>>>(ctxh, ctxl, woh, wol, bo, x, gt0, NTOK, DM, DM, 2);
    ln_kernel<<<NTOK, 256>>>(gt0, g1, be1, gx1);
    conv_act<<<(NTOK * DM) / 1024, 256>>>(gx1, x1h, x1l);

    // ---- FFN ----
    mma_gemm<<<dim3(DFF / 128, NTOK / 128), 256, SMEM_MMA>>>(x1h, x1l, w1h, w1l, b1, nullptr, gff, NTOK, DFF, DM, 1);
    conv_act<<<((size_t)NTOK * DFF) / 1024, 256>>>(gff, ffh, ffl);
    mma_gemm<<<dim3(DM / 128, NTOK / 128), 256, SMEM_MMA>>>(ffh, ffl, w2h, w2l, b2, gx1, gt0, NTOK, DM, DFF, 2);
    ln_kernel<<<NTOK, 256>>>(gt0, g2, be2, out);
}

// round 9
// speedup vs baseline: 2.7040x; 1.3496x over previous
#include <cuda_runtime.h>
#include <cuda_bf16.h>
#include <cstdint>

#define NTOK 4096   // B*L
#define DM   1024
#define DFF  4096
#define SEQ  2048

// ---------------- scratch (device globals: allocation-free) ----------------
__device__ float g_t0[NTOK * DM];
__device__ float g_x1[NTOK * DM];

// bf16 hi/lo buffers
__device__ __nv_bfloat16 g_xh[NTOK * DM],  g_xl[NTOK * DM];
__device__ __nv_bfloat16 g_qh[NTOK * DM],  g_ql[NTOK * DM];
__device__ __nv_bfloat16 g_kh[NTOK * DM],  g_kl[NTOK * DM];
__device__ __nv_bfloat16 g_vh[NTOK * DM],  g_vl[NTOK * DM];
__device__ __nv_bfloat16 g_ctxh[NTOK * DM], g_ctxl[NTOK * DM];
__device__ __nv_bfloat16 g_x1h[NTOK * DM], g_x1l[NTOK * DM];
__device__ __nv_bfloat16 g_ffh[(size_t)NTOK * DFF], g_ffl[(size_t)NTOK * DFF];
// transposed weights [N,K] bf16 hi/lo
__device__ __nv_bfloat16 g_wqh[DM * DM], g_wql[DM * DM];
__device__ __nv_bfloat16 g_wkh[DM * DM], g_wkl[DM * DM];
__device__ __nv_bfloat16 g_wvh[DM * DM], g_wvl[DM * DM];
__device__ __nv_bfloat16 g_woh[DM * DM], g_wol[DM * DM];
__device__ __nv_bfloat16 g_w1h[(size_t)DFF * DM], g_w1l[(size_t)DFF * DM];
__device__ __nv_bfloat16 g_w2h[(size_t)DM * DFF], g_w2l[(size_t)DM * DFF];

// ---------------- PTX helpers (family-portable; NO tcgen05) ----------------
__device__ __forceinline__ uint32_t smem_u32(const void* p) {
    uint32_t a;
    asm("{ .reg .u64 t; cvta.to.shared.u64 t, %1; cvt.u32.u64 %0, t; }" : "=r"(a) : "l"(p));
    return a;
}
__device__ __forceinline__ void cpasync16(uint32_t dst, const void* src) {
    asm volatile("cp.async.cg.shared.global [%0], [%1], 16;" :: "r"(dst), "l"(src));
}
__device__ __forceinline__ void ldsm4(uint32_t (&r)[4], uint32_t addr) {
    asm volatile("ldmatrix.sync.aligned.m8n8.x4.shared.b16 {%0,%1,%2,%3}, [%4];"
        : "=r"(r[0]), "=r"(r[1]), "=r"(r[2]), "=r"(r[3]) : "r"(addr));
}
__device__ __forceinline__ void ldsm4t(uint32_t (&r)[4], uint32_t addr) {
    asm volatile("ldmatrix.sync.aligned.m8n8.x4.trans.shared.b16 {%0,%1,%2,%3}, [%4];"
        : "=r"(r[0]), "=r"(r[1]), "=r"(r[2]), "=r"(r[3]) : "r"(addr));
}
__device__ __forceinline__ void mma16816(float (&c)[4], const uint32_t (&a)[4],
                                         uint32_t b0, uint32_t b1) {
    asm volatile("mma.sync.aligned.m16n8k16.row.col.f32.bf16.bf16.f32 "
        "{%0,%1,%2,%3}, {%4,%5,%6,%7}, {%8,%9}, {%0,%1,%2,%3};"
        : "+f"(c[0]), "+f"(c[1]), "+f"(c[2]), "+f"(c[3])
        : "r"(a[0]), "r"(a[1]), "r"(a[2]), "r"(a[3]), "r"(b0), "r"(b1));
}
__device__ __forceinline__ uint32_t b2u(__nv_bfloat162 v) {
    return *reinterpret_cast<uint32_t*>(&v);
}
// split two floats into packed bf16x2 hi + lo-residual
__device__ __forceinline__ void split_pack2(float a, float b, uint32_t& h, uint32_t& l) {
    __nv_bfloat162 hh = __floats2bfloat162_rn(a, b);
    h = b2u(hh);
    float ra = a - __bfloat162float(hh.x);
    float rb = b - __bfloat162float(hh.y);
    __nv_bfloat162 ll = __floats2bfloat162_rn(ra, rb);
    l = b2u(ll);
}

__device__ __forceinline__ uint32_t swz64(uint32_t off)  { return off ^ ((off >> 3) & 0x30); }
__device__ __forceinline__ uint32_t swz128(uint32_t off) { return off ^ ((off >> 3) & 0x70); }

// =====================================================================
// mma_gemm: C = (Ah+Al)[M,K] @ (Bh+Bl)[N,K]^T + bias
// epi: 0=none, 1=GELU(exact), 2=+res. Outputs: Cf (fp32) and/or Ch/Cl (bf16 split).
// 128x128 CTA tile, BK=32, 3-stage cp.async, 8 warps (32m x 64n).
// =====================================================================
#define TILEB  8192
#define STAGEB (4 * TILEB)
#define SMEM_MMA (3 * STAGEB + 1024)

__global__ __launch_bounds__(256, 1)
void mma_gemm(const __nv_bfloat16* __restrict__ Ah, const __nv_bfloat16* __restrict__ Al,
              const __nv_bfloat16* __restrict__ Bh, const __nv_bfloat16* __restrict__ Bl,
              const float* __restrict__ bias, const float* __restrict__ res,
              float* __restrict__ Cf, __nv_bfloat16* __restrict__ Ch,
              __nv_bfloat16* __restrict__ Cl,
              int M, int N, int K, int epi)
{
    extern __shared__ char smem[];
    const uint32_t s0 = (smem_u32(smem) + 1023) & ~1023u;

    const int tid = threadIdx.x;
    const int wid = tid >> 5, lid = tid & 31;
    const int brow = blockIdx.y << 7, bcol = blockIdx.x << 7;
    const int mw = (wid & 3) << 5;
    const int nw = (wid >> 2) << 6;

    const int lrow = tid >> 1;
    const int q0   = (tid & 1) << 1;
    const uint32_t sw0 = swz64(lrow * 64 + q0 * 16);
    const uint32_t sw1 = swz64(lrow * 64 + q0 * 16 + 16);
    const size_t ga = (size_t)(brow + lrow) * K + q0 * 8;
    const size_t gb = (size_t)(bcol + lrow) * K + q0 * 8;

    const int nchunk = K >> 5;

    auto issue = [&](int c) {
        const uint32_t st = s0 + (uint32_t)(c % 3) * STAGEB;
        const size_t k0 = (size_t)c << 5;
        cpasync16(st + 0 * TILEB + sw0, Ah + ga + k0);
        cpasync16(st + 0 * TILEB + sw1, Ah + ga + k0 + 8);
        cpasync16(st + 1 * TILEB + sw0, Al + ga + k0);
        cpasync16(st + 1 * TILEB + sw1, Al + ga + k0 + 8);
        cpasync16(st + 2 * TILEB + sw0, Bh + gb + k0);
        cpasync16(st + 2 * TILEB + sw1, Bh + gb + k0 + 8);
        cpasync16(st + 3 * TILEB + sw0, Bl + gb + k0);
        cpasync16(st + 3 * TILEB + sw1, Bl + gb + k0 + 8);
    };

    issue(0);
    asm volatile("cp.async.commit_group;");
    issue(1);
    asm volatile("cp.async.commit_group;");

    float acc[2][8][4];
#pragma unroll
    for (int i = 0; i < 2; i++)
#pragma unroll
        for (int j = 0; j < 8; j++)
#pragma unroll
            for (int t = 0; t < 4; t++) acc[i][j][t] = 0.f;

    const int a_row = lid & 15;
    const int a_h   = lid >> 4;
    const int b_row = (lid & 7) + ((lid >> 4) << 3);
    const int b_h   = (lid >> 3) & 1;

    for (int c = 0; c < nchunk; c++) {
        asm volatile("cp.async.wait_group 1;");
        __syncthreads();
        if (c + 2 < nchunk) issue(c + 2);
        asm volatile("cp.async.commit_group;");

        const uint32_t st  = s0 + (uint32_t)(c % 3) * STAGEB;
        const uint32_t sAh = st, sAl = st + TILEB;
        const uint32_t sBh = st + 2 * TILEB, sBl = st + 3 * TILEB;

#pragma unroll
        for (int ks = 0; ks < 2; ks++) {
            uint32_t ah[2][4], al[2][4];
#pragma unroll
            for (int i = 0; i < 2; i++) {
                uint32_t off = swz64((mw + i * 16 + a_row) * 64 + ks * 32 + a_h * 16);
                ldsm4(ah[i], sAh + off);
                ldsm4(al[i], sAl + off);
            }
            uint32_t bh[8][2], bl[8][2];
#pragma unroll
            for (int j = 0; j < 4; j++) {
                uint32_t off = swz64((nw + j * 16 + b_row) * 64 + ks * 32 + b_h * 16);
                uint32_t t0[4], t1[4];
                ldsm4(t0, sBh + off);
                ldsm4(t1, sBl + off);
                bh[2*j][0] = t0[0]; bh[2*j][1] = t0[1]; bh[2*j+1][0] = t0[2]; bh[2*j+1][1] = t0[3];
                bl[2*j][0] = t1[0]; bl[2*j][1] = t1[1]; bl[2*j+1][0] = t1[2]; bl[2*j+1][1] = t1[3];
            }
#pragma unroll
            for (int i = 0; i < 2; i++)
#pragma unroll
                for (int j = 0; j < 8; j++) {
                    mma16816(acc[i][j], ah[i], bh[j][0], bh[j][1]);
                    mma16816(acc[i][j], ah[i], bl[j][0], bl[j][1]);
                    mma16816(acc[i][j], al[i], bh[j][0], bh[j][1]);
                }
        }
    }

    // ---- epilogue ----
    const int erow = lid >> 2;
    const int ecol = (lid & 3) << 1;
#pragma unroll
    for (int i = 0; i < 2; i++)
#pragma unroll
        for (int j = 0; j < 8; j++)
#pragma unroll
            for (int h = 0; h < 2; h++) {
                const int m = brow + mw + i * 16 + erow + h * 8;
                const int n = bcol + nw + j * 8 + ecol;
                float v0 = acc[i][j][h * 2 + 0] + bias[n];
                float v1 = acc[i][j][h * 2 + 1] + bias[n + 1];
                const size_t off = (size_t)m * N + n;
                if (epi == 1) {
                    v0 = 0.5f * v0 * (1.0f + erff(v0 * 0.70710678118654752f));
                    v1 = 0.5f * v1 * (1.0f + erff(v1 * 0.70710678118654752f));
                } else if (epi == 2) {
                    float2 rr = *(const float2*)&res[off];
                    v0 += rr.x; v1 += rr.y;
                }
                if (Cf) *(float2*)&Cf[off] = make_float2(v0, v1);
                if (Ch) {
                    uint32_t hh, ll;
                    split_pack2(v0, v1, hh, ll);
                    *(uint32_t*)&Ch[off] = hh;
                    *(uint32_t*)&Cl[off] = ll;
                }
            }
}

// =====================================================================
// Causal flash attention via HMMA bf16 hi/lo split. fp32 softmax.
// 128 q-rows per block, kv tiles of 64, 8 warps, 3-stage cp.async.
// =====================================================================
#define ATT_STAGEB 32768        // Kh,Kl,Vh,Vl each 64x128B = 8KB
#define SMEM_ATT (1024 + 32768 + 3 * ATT_STAGEB)

__global__ __launch_bounds__(256, 1)
void attn_mma(const __nv_bfloat16* __restrict__ Qh, const __nv_bfloat16* __restrict__ Ql,
              const __nv_bfloat16* __restrict__ Kh, const __nv_bfloat16* __restrict__ Kl,
              const __nv_bfloat16* __restrict__ Vh, const __nv_bfloat16* __restrict__ Vl,
              __nv_bfloat16* __restrict__ Oh, __nv_bfloat16* __restrict__ Ol)
{
    extern __shared__ char sm[];
    const uint32_t sQh = (smem_u32(sm) + 1023) & ~1023u;
    const uint32_t sQl = sQh + 16384;
    const uint32_t sKV = sQh + 32768;

    const int tid = threadIdx.x, wid = tid >> 5, lid = tid & 31;
    const int qt = (int)gridDim.x - 1 - (int)blockIdx.x;   // heavy first
    const int bh = blockIdx.y;
    const int b = bh >> 4, h = bh & 15;
    const int qbase = qt * 128;
    const size_t tok0 = (size_t)b * SEQ;
    const size_t hoff = (size_t)h * 64;
    const int mw = wid * 16;

    // ---- Q load (once, both precisions) ----
    {
        const int r = tid >> 1;
        const int half = tid & 1;
        const size_t g = (tok0 + qbase + r) * DM + hoff + half * 32;
#pragma unroll
        for (int i = 0; i < 4; i++) {
            uint32_t so = swz128(r * 128 + half * 64 + i * 16);
            cpasync16(sQh + so, Qh + g + i * 8);
            cpasync16(sQl + so, Ql + g + i * 8);
        }
    }

    const int njt = 2 * qt + 2;
    const int kr = tid >> 2;
    const int kq = tid & 3;
    const uint32_t kso0 = swz128(kr * 128 + kq * 32);
    const uint32_t kso1 = swz128(kr * 128 + kq * 32 + 16);

    auto issue_kv = [&](int jt) {
        const uint32_t st = sKV + (uint32_t)(jt % 3) * ATT_STAGEB;
        const size_t g = (tok0 + jt * 64 + kr) * DM + hoff + kq * 16;
        cpasync16(st +         kso0, Kh + g);
        cpasync16(st +         kso1, Kh + g + 8);
        cpasync16(st +  8192 + kso0, Kl + g);
        cpasync16(st +  8192 + kso1, Kl + g + 8);
        cpasync16(st + 16384 + kso0, Vh + g);
        cpasync16(st + 16384 + kso1, Vh + g + 8);
        cpasync16(st + 24576 + kso0, Vl + g);
        cpasync16(st + 24576 + kso1, Vl + g + 8);
    };

    issue_kv(0);
    asm volatile("cp.async.commit_group;");
    issue_kv(1);
    asm volatile("cp.async.commit_group;");

    float O[8][4];
#pragma unroll
    for (int j = 0; j < 8; j++)
#pragma unroll
        for (int e = 0; e < 4; e++) O[j][e] = 0.f;
    float m0 = -1e30f, m1 = -1e30f, l0 = 0.f, l1 = 0.f;

    const int rql = lid >> 2;
    const int cql = (lid & 3) * 2;
    const int row0g = qbase + mw + rql;
    const int row1g = row0g + 8;

    for (int jt = 0; jt < njt; jt++) {
        asm volatile("cp.async.wait_group 1;");
        __syncthreads();
        if (jt + 2 < njt) issue_kv(jt + 2);
        asm volatile("cp.async.commit_group;");

        const bool active = !(mw < 64 && jt == njt - 1);   // fully-masked tile skip
        if (active) {
            const uint32_t stKh = sKV + (uint32_t)(jt % 3) * ATT_STAGEB;
            const uint32_t stKl = stKh + 8192;
            const uint32_t stVh = stKh + 16384, stVl = stKh + 24576;

            float S[8][4];
#pragma unroll
            for (int j = 0; j < 8; j++)
#pragma unroll
                for (int e = 0; e < 4; e++) S[j][e] = 0.f;

            // ---- S = Q K^T (split) ----
#pragma unroll
            for (int ks = 0; ks < 4; ks++) {
                uint32_t qh4[4], ql4[4];
                uint32_t qoff = swz128((mw + (lid & 15)) * 128 + ks * 32 + (lid >> 4) * 16);
                ldsm4(qh4, sQh + qoff);
                ldsm4(ql4, sQl + qoff);
                uint32_t kfh[8][2], kfl[8][2];
#pragma unroll
                for (int jj = 0; jj < 4; jj++) {
                    uint32_t koff = swz128((jj * 16 + (lid & 7) + ((lid >> 4) << 3)) * 128
                                           + ks * 32 + ((lid >> 3) & 1) * 16);
                    uint32_t t0[4], t1[4];
                    ldsm4(t0, stKh + koff);
                    ldsm4(t1, stKl + koff);
                    kfh[2*jj][0]=t0[0]; kfh[2*jj][1]=t0[1]; kfh[2*jj+1][0]=t0[2]; kfh[2*jj+1][1]=t0[3];
                    kfl[2*jj][0]=t1[0]; kfl[2*jj][1]=t1[1]; kfl[2*jj+1][0]=t1[2]; kfl[2*jj+1][1]=t1[3];
                }
#pragma unroll
                for (int j = 0; j < 8; j++) mma16816(S[j], qh4, kfh[j][0], kfh[j][1]);
#pragma unroll
                for (int j = 0; j < 8; j++) mma16816(S[j], qh4, kfl[j][0], kfl[j][1]);
#pragma unroll
                for (int j = 0; j < 8; j++) mma16816(S[j], ql4, kfh[j][0], kfh[j][1]);
            }

            // ---- scale + causal mask ----
            const int colb = jt * 64;
            const bool diag = (jt >= 2 * qt);
#pragma unroll
            for (int j = 0; j < 8; j++)
#pragma unroll
                for (int e = 0; e < 4; e++) {
                    float v = S[j][e] * 0.125f;
                    if (diag) {
                        int col = colb + 8 * j + cql + (e & 1);
                        int row = (e < 2) ? row0g : row1g;
                        if (col > row) v = -1e30f;
                    }
                    S[j][e] = v;
                }

            // ---- online softmax (rows r, r+8; groups of 4 lanes) ----
            float rm0 = -1e30f, rm1 = -1e30f;
#pragma unroll
            for (int j = 0; j < 8; j++) {
                rm0 = fmaxf(rm0, fmaxf(S[j][0], S[j][1]));
                rm1 = fmaxf(rm1, fmaxf(S[j][2], S[j][3]));
            }
            rm0 = fmaxf(rm0, __shfl_xor_sync(0xffffffffu, rm0, 1));
            rm0 = fmaxf(rm0, __shfl_xor_sync(0xffffffffu, rm0, 2));
            rm1 = fmaxf(rm1, __shfl_xor_sync(0xffffffffu, rm1, 1));
            rm1 = fmaxf(rm1, __shfl_xor_sync(0xffffffffu, rm1, 2));
            float mn0 = fmaxf(m0, rm0), mn1 = fmaxf(m1, rm1);
            float a0 = __expf(m0 - mn0), a1 = __expf(m1 - mn1);
            m0 = mn0; m1 = mn1;
            float rs0 = 0.f, rs1 = 0.f;
#pragma unroll
            for (int j = 0; j < 8; j++) {
                S[j][0] = __expf(S[j][0] - mn0);
                S[j][1] = __expf(S[j][1] - mn0);
                S[j][2] = __expf(S[j][2] - mn1);
                S[j][3] = __expf(S[j][3] - mn1);
                rs0 += S[j][0] + S[j][1];
                rs1 += S[j][2] + S[j][3];
            }
            rs0 += __shfl_xor_sync(0xffffffffu, rs0, 1);
            rs0 += __shfl_xor_sync(0xffffffffu, rs0, 2);
            rs1 += __shfl_xor_sync(0xffffffffu, rs1, 1);
            rs1 += __shfl_xor_sync(0xffffffffu, rs1, 2);
            l0 = l0 * a0 + rs0;
            l1 = l1 * a1 + rs1;
#pragma unroll
            for (int j = 0; j < 8; j++) {
                O[j][0] *= a0; O[j][1] *= a0; O[j][2] *= a1; O[j][3] *= a1;
            }

            // ---- split P into A-fragments ----
            uint32_t pah[4][4], pal[4][4];
#pragma unroll
            for (int ks = 0; ks < 4; ks++) {
                split_pack2(S[2*ks][0],   S[2*ks][1],   pah[ks][0], pal[ks][0]);
                split_pack2(S[2*ks][2],   S[2*ks][3],   pah[ks][1], pal[ks][1]);
                split_pack2(S[2*ks+1][0], S[2*ks+1][1], pah[ks][2], pal[ks][2]);
                split_pack2(S[2*ks+1][2], S[2*ks+1][3], pah[ks][3], pal[ks][3]);
            }

            // ---- O += P V (split) ----
#pragma unroll
            for (int ks = 0; ks < 4; ks++) {
                uint32_t vfh[8][2], vfl[8][2];
                const int rowv = ks * 16 + ((lid >> 3) & 1) * 8 + (lid & 7);
                const int colv = (lid >> 4) * 16;
#pragma unroll
                for (int nb = 0; nb < 4; nb++) {
                    uint32_t voff = swz128(rowv * 128 + nb * 32 + colv);
                    uint32_t t0[4], t1[4];
                    ldsm4t(t0, stVh + voff);
                    ldsm4t(t1, stVl + voff);
                    vfh[2*nb][0]=t0[0]; vfh[2*nb][1]=t0[1]; vfh[2*nb+1][0]=t0[2]; vfh[2*nb+1][1]=t0[3];
                    vfl[2*nb][0]=t1[0]; vfl[2*nb][1]=t1[1]; vfl[2*nb+1][0]=t1[2]; vfl[2*nb+1][1]=t1[3];
                }
#pragma unroll
                for (int j = 0; j < 8; j++) mma16816(O[j], pah[ks], vfh[j][0], vfh[j][1]);
#pragma unroll
                for (int j = 0; j < 8; j++) mma16816(O[j], pah[ks], vfl[j][0], vfl[j][1]);
#pragma unroll
                for (int j = 0; j < 8; j++) mma16816(O[j], pal[ks], vfh[j][0], vfh[j][1]);
            }
        }
    }

    // ---- epilogue: normalize + split-write ctx ----
    const float inv0 = 1.0f / l0, inv1 = 1.0f / l1;
    const size_t tq0 = (tok0 + row0g) * DM + hoff;
    const size_t tq1 = (tok0 + row1g) * DM + hoff;
#pragma unroll
    for (int j = 0; j < 8; j++) {
        const int c = 8 * j + cql;
        uint32_t hh, ll;
        split_pack2(O[j][0] * inv0, O[j][1] * inv0, hh, ll);
        *(uint32_t*)&Oh[tq0 + c] = hh;
        *(uint32_t*)&Ol[tq0 + c] = ll;
        split_pack2(O[j][2] * inv1, O[j][3] * inv1, hh, ll);
        *(uint32_t*)&Oh[tq1 + c] = hh;
        *(uint32_t*)&Ol[tq1 + c] = ll;
    }
}

// =====================================================================
// conversions
// =====================================================================
__device__ __forceinline__ void split_bf16(float v, __nv_bfloat16& h, __nv_bfloat16& l) {
    h = __float2bfloat16(v);
    l = __float2bfloat16(v - __bfloat162float(h));
}

__global__ __launch_bounds__(256)
void conv_act(const float* __restrict__ in, __nv_bfloat16* __restrict__ hi,
              __nv_bfloat16* __restrict__ lo)
{
    const size_t i = ((size_t)blockIdx.x * 256 + threadIdx.x) * 4;
    float4 v = *(const float4*)(in + i);
    uint32_t h0, l0, h1, l1;
    split_pack2(v.x, v.y, h0, l0);
    split_pack2(v.z, v.w, h1, l1);
    *(uint32_t*)&hi[i]     = h0;
    *(uint32_t*)&hi[i + 2] = h1;
    *(uint32_t*)&lo[i]     = l0;
    *(uint32_t*)&lo[i + 2] = l1;
}

// transpose W[K,N] -> hi/lo [N,K]
__global__ __launch_bounds__(256)
void conv_wT(const float* __restrict__ W, __nv_bfloat16* __restrict__ hi,
             __nv_bfloat16* __restrict__ lo, int K, int N)
{
    __shared__ float t[32][33];
    const int n0 = blockIdx.x * 32, k0 = blockIdx.y * 32;
    const int tx = threadIdx.x & 31, ty = threadIdx.x >> 5;
#pragma unroll
    for (int j = 0; j < 4; j++)
        t[ty + 8 * j][tx] = W[(size_t)(k0 + ty + 8 * j) * N + n0 + tx];
    __syncthreads();
#pragma unroll
    for (int j = 0; j < 4; j++) {
        float v = t[tx][ty + 8 * j];
        __nv_bfloat16 h, l;
        split_bf16(v, h, l);
        size_t o = (size_t)(n0 + ty + 8 * j) * K + k0 + tx;
        hi[o] = h; lo[o] = l;
    }
}

// =====================================================================
// LayerNorm (+ optional bf16 hi/lo split out)
// =====================================================================
__global__ __launch_bounds__(256)
void ln_kernel(const float* __restrict__ in, const float* __restrict__ gamma,
               const float* __restrict__ beta, float* __restrict__ out,
               __nv_bfloat16* __restrict__ oh, __nv_bfloat16* __restrict__ ol)
{
    __shared__ float rs[8], rs2[8];
    const int row = blockIdx.x;
    const int t = threadIdx.x;
    float4 v = ((const float4*)(in + (size_t)row * DM))[t];
    float s  = v.x + v.y + v.z + v.w;
    float s2 = v.x * v.x + v.y * v.y + v.z * v.z + v.w * v.w;
#pragma unroll
    for (int off = 16; off; off >>= 1) {
        s  += __shfl_xor_sync(0xffffffffu, s, off);
        s2 += __shfl_xor_sync(0xffffffffu, s2, off);
    }
    if ((t & 31) == 0) { rs[t >> 5] = s; rs2[t >> 5] = s2; }
    __syncthreads();
    float ts = 0.f, ts2 = 0.f;
#pragma unroll
    for (int w = 0; w < 8; w++) { ts += rs[w]; ts2 += rs2[w]; }
    float mu   = ts * (1.0f / DM);
    float var  = ts2 * (1.0f / DM) - mu * mu;
    float rstd = rsqrtf(var + 1e-5f);
    float4 g4 = ((const float4*)gamma)[t];
    float4 b4 = ((const float4*)beta)[t];
    float4 o4;
    o4.x = (v.x - mu) * rstd * g4.x + b4.x;
    o4.y = (v.y - mu) * rstd * g4.y + b4.y;
    o4.z = (v.z - mu) * rstd * g4.z + b4.z;
    o4.w = (v.w - mu) * rstd * g4.w + b4.w;
    ((float4*)(out + (size_t)row * DM))[t] = o4;
    if (oh) {
        const size_t i = (size_t)row * DM + t * 4;
        uint32_t h0, l0, h1, l1;
        split_pack2(o4.x, o4.y, h0, l0);
        split_pack2(o4.z, o4.w, h1, l1);
        *(uint32_t*)&oh[i]     = h0;
        *(uint32_t*)&oh[i + 2] = h1;
        *(uint32_t*)&ol[i]     = l0;
        *(uint32_t*)&ol[i + 2] = l1;
    }
}

// =====================================================================
extern "C" void kernel_launch(void* const* d_in, const int* in_sizes, int n_in,
                              void* d_out, int out_size)
{
    (void)in_sizes; (void)n_in; (void)out_size;
    const float* x   = (const float*)d_in[0];
    const float* Wq  = (const float*)d_in[1];
    const float* bq  = (const float*)d_in[2];
    const float* Wk  = (const float*)d_in[3];
    const float* bk  = (const float*)d_in[4];
    const float* Wv  = (const float*)d_in[5];
    const float* bv  = (const float*)d_in[6];
    const float* Wo  = (const float*)d_in[7];
    const float* bo  = (const float*)d_in[8];
    const float* W1  = (const float*)d_in[9];
    const float* b1  = (const float*)d_in[10];
    const float* W2  = (const float*)d_in[11];
    const float* b2  = (const float*)d_in[12];
    const float* g1  = (const float*)d_in[13];
    const float* be1 = (const float*)d_in[14];
    const float* g2  = (const float*)d_in[15];
    const float* be2 = (const float*)d_in[16];
    float* out = (float*)d_out;

    float *gt0, *gx1;
    cudaGetSymbolAddress((void**)&gt0, g_t0);
    cudaGetSymbolAddress((void**)&gx1, g_x1);

    __nv_bfloat16 *xh, *xl, *qh, *ql, *kh, *kl, *vh, *vl, *ctxh, *ctxl, *x1h, *x1l, *ffh, *ffl;
    __nv_bfloat16 *wqh, *wql, *wkh, *wkl, *wvh, *wvl, *woh, *wol, *w1h, *w1l, *w2h, *w2l;
    cudaGetSymbolAddress((void**)&xh,   g_xh);   cudaGetSymbolAddress((void**)&xl,   g_xl);
    cudaGetSymbolAddress((void**)&qh,   g_qh);   cudaGetSymbolAddress((void**)&ql,   g_ql);
    cudaGetSymbolAddress((void**)&kh,   g_kh);   cudaGetSymbolAddress((void**)&kl,   g_kl);
    cudaGetSymbolAddress((void**)&vh,   g_vh);   cudaGetSymbolAddress((void**)&vl,   g_vl);
    cudaGetSymbolAddress((void**)&ctxh, g_ctxh); cudaGetSymbolAddress((void**)&ctxl, g_ctxl);
    cudaGetSymbolAddress((void**)&x1h,  g_x1h);  cudaGetSymbolAddress((void**)&x1l,  g_x1l);
    cudaGetSymbolAddress((void**)&ffh,  g_ffh);  cudaGetSymbolAddress((void**)&ffl,  g_ffl);
    cudaGetSymbolAddress((void**)&wqh,  g_wqh);  cudaGetSymbolAddress((void**)&wql,  g_wql);
    cudaGetSymbolAddress((void**)&wkh,  g_wkh);  cudaGetSymbolAddress((void**)&wkl,  g_wkl);
    cudaGetSymbolAddress((void**)&wvh,  g_wvh);  cudaGetSymbolAddress((void**)&wvl,  g_wvl);
    cudaGetSymbolAddress((void**)&woh,  g_woh);  cudaGetSymbolAddress((void**)&wol,  g_wol);
    cudaGetSymbolAddress((void**)&w1h,  g_w1h);  cudaGetSymbolAddress((void**)&w1l,  g_w1l);
    cudaGetSymbolAddress((void**)&w2h,  g_w2h);  cudaGetSymbolAddress((void**)&w2l,  g_w2l);

    cudaFuncSetAttribute(mma_gemm, cudaFuncAttributeMaxDynamicSharedMemorySize, SMEM_MMA);
    cudaFuncSetAttribute(attn_mma, cudaFuncAttributeMaxDynamicSharedMemorySize, SMEM_ATT);

    // ---- weight transpose+split ----
    conv_wT<<<dim3(DM / 32,  DM / 32),  256>>>(Wq, wqh, wql, DM, DM);
    conv_wT<<<dim3(DM / 32,  DM / 32),  256>>>(Wk, wkh, wkl, DM, DM);
    conv_wT<<<dim3(DM / 32,  DM / 32),  256>>>(Wv, wvh, wvl, DM, DM);
    conv_wT<<<dim3(DM / 32,  DM / 32),  256>>>(Wo, woh, wol, DM, DM);
    conv_wT<<<dim3(DFF / 32, DM / 32),  256>>>(W1, w1h, w1l, DM, DFF);
    conv_wT<<<dim3(DM / 32,  DFF / 32), 256>>>(W2, w2h, w2l, DFF, DM);

    // ---- x split ----
    conv_act<<<(NTOK * DM) / 1024, 256>>>(x, xh, xl);

    // ---- QKV (split bf16 outputs only) ----
    mma_gemm<<<dim3(DM / 128, NTOK / 128), 256, SMEM_MMA>>>(xh, xl, wqh, wql, bq, nullptr, nullptr, qh, ql, NTOK, DM, DM, 0);
    mma_gemm<<<dim3(DM / 128, NTOK / 128), 256, SMEM_MMA>>>(xh, xl, wkh, wkl, bk, nullptr, nullptr, kh, kl, NTOK, DM, DM, 0);
    mma_gemm<<<dim3(DM / 128, NTOK / 128), 256, SMEM_MMA>>>(xh, xl, wvh, wvl, bv, nullptr, nullptr, vh, vl, NTOK, DM, DM, 0);

    // ---- attention (HMMA) ----
    attn_mma<<<dim3(SEQ / 128, 32), 256, SMEM_ATT>>>(qh, ql, kh, kl, vh, vl, ctxh, ctxl);

    // ---- Wo + residual, LN1 (+split) ----
    mma_gemm<<<dim3(DM / 128, NTOK / 128), 256, SMEM_MMA>>>(ctxh, ctxl, woh, wol, bo, x, gt0, nullptr, nullptr, NTOK, DM, DM, 2);
    ln_kernel<<<NTOK, 256>>>(gt0, g1, be1, gx1, x1h, x1l);

    // ---- FFN ----
    mma_gemm<<<dim3(DFF / 128, NTOK / 128), 256, SMEM_MMA>>>(x1h, x1l, w1h, w1l, b1, nullptr, nullptr, ffh, ffl, NTOK, DFF, DM, 1);
    mma_gemm<<<dim3(DM / 128, NTOK / 128), 256, SMEM_MMA>>>(ffh, ffl, w2h, w2l, b2, gx1, gt0, nullptr, nullptr, NTOK, DM, DFF, 2);
    ln_kernel<<<NTOK, 256>>>(gt0, g2, be2, out, nullptr, nullptr);
}

// round 10
// speedup vs baseline: 2.7620x; 1.0214x over previous
#include <cuda_runtime.h>
#include <cuda_bf16.h>
#include <cstdint>

#define NTOK 4096   // B*L
#define DM   1024
#define DFF  4096
#define SEQ  2048

// ---------------- scratch (device globals: allocation-free) ----------------
__device__ float g_t0[NTOK * DM];
__device__ float g_x1[NTOK * DM];

__device__ __nv_bfloat16 g_xh[NTOK * DM],  g_xl[NTOK * DM];
__device__ __nv_bfloat16 g_qh[NTOK * DM],  g_ql[NTOK * DM];
__device__ __nv_bfloat16 g_kh[NTOK * DM],  g_kl[NTOK * DM];
__device__ __nv_bfloat16 g_vh[NTOK * DM],  g_vl[NTOK * DM];
__device__ __nv_bfloat16 g_ctxh[NTOK * DM], g_ctxl[NTOK * DM];
__device__ __nv_bfloat16 g_x1h[NTOK * DM], g_x1l[NTOK * DM];
__device__ __nv_bfloat16 g_ffh[(size_t)NTOK * DFF], g_ffl[(size_t)NTOK * DFF];
// fused QKV transposed weights [3*DM, DM] hi/lo + combined bias
__device__ __nv_bfloat16 g_wqkvh[3 * DM * DM], g_wqkvl[3 * DM * DM];
__device__ float g_bqkv[3 * DM];
__device__ __nv_bfloat16 g_woh[DM * DM], g_wol[DM * DM];
__device__ __nv_bfloat16 g_w1h[(size_t)DFF * DM], g_w1l[(size_t)DFF * DM];
__device__ __nv_bfloat16 g_w2h[(size_t)DM * DFF], g_w2l[(size_t)DM * DFF];

// ---------------- PTX helpers (family-portable; NO tcgen05) ----------------
__device__ __forceinline__ uint32_t smem_u32(const void* p) {
    uint32_t a;
    asm("{ .reg .u64 t; cvta.to.shared.u64 t, %1; cvt.u32.u64 %0, t; }" : "=r"(a) : "l"(p));
    return a;
}
__device__ __forceinline__ void cpasync16(uint32_t dst, const void* src) {
    asm volatile("cp.async.cg.shared.global [%0], [%1], 16;" :: "r"(dst), "l"(src));
}
__device__ __forceinline__ void ldsm4(uint32_t (&r)[4], uint32_t addr) {
    asm volatile("ldmatrix.sync.aligned.m8n8.x4.shared.b16 {%0,%1,%2,%3}, [%4];"
        : "=r"(r[0]), "=r"(r[1]), "=r"(r[2]), "=r"(r[3]) : "r"(addr));
}
__device__ __forceinline__ void ldsm4t(uint32_t (&r)[4], uint32_t addr) {
    asm volatile("ldmatrix.sync.aligned.m8n8.x4.trans.shared.b16 {%0,%1,%2,%3}, [%4];"
        : "=r"(r[0]), "=r"(r[1]), "=r"(r[2]), "=r"(r[3]) : "r"(addr));
}
__device__ __forceinline__ void mma16816(float (&c)[4], const uint32_t (&a)[4],
                                         uint32_t b0, uint32_t b1) {
    asm volatile("mma.sync.aligned.m16n8k16.row.col.f32.bf16.bf16.f32 "
        "{%0,%1,%2,%3}, {%4,%5,%6,%7}, {%8,%9}, {%0,%1,%2,%3};"
        : "+f"(c[0]), "+f"(c[1]), "+f"(c[2]), "+f"(c[3])
        : "r"(a[0]), "r"(a[1]), "r"(a[2]), "r"(a[3]), "r"(b0), "r"(b1));
}
__device__ __forceinline__ uint32_t b2u(__nv_bfloat162 v) {
    return *reinterpret_cast<uint32_t*>(&v);
}
__device__ __forceinline__ void split_pack2(float a, float b, uint32_t& h, uint32_t& l) {
    __nv_bfloat162 hh = __floats2bfloat162_rn(a, b);
    h = b2u(hh);
    float ra = a - __bfloat162float(hh.x);
    float rb = b - __bfloat162float(hh.y);
    __nv_bfloat162 ll = __floats2bfloat162_rn(ra, rb);
    l = b2u(ll);
}
__device__ __forceinline__ uint32_t swz128(uint32_t off) { return off ^ ((off >> 3) & 0x70); }

// =====================================================================
// mma_gemm: C = (Ah+Al)[M,K] @ (Bh+Bl)[N,K]^T + bias
// epi: 0=none, 1=GELU, 2=+res. fused!=0: N=3072 QKV, route per 1024-col block.
// 128x128 CTA tile, BK=64, 3-stage cp.async, 8 warps (32m x 64n).
// =====================================================================
#define GTILEB 16384                  // 128 rows x 128 B
#define GSTAGEB (4 * GTILEB)          // Ah, Al, Bh, Bl = 64 KB
#define SMEM_MMA (3 * GSTAGEB + 1024)

__global__ __launch_bounds__(256, 1)
void mma_gemm(const __nv_bfloat16* __restrict__ Ah, const __nv_bfloat16* __restrict__ Al,
              const __nv_bfloat16* __restrict__ Bh, const __nv_bfloat16* __restrict__ Bl,
              const float* __restrict__ bias, const float* __restrict__ res,
              float* __restrict__ Cf,
              __nv_bfloat16* __restrict__ Ch0, __nv_bfloat16* __restrict__ Cl0,
              __nv_bfloat16* __restrict__ Ch1, __nv_bfloat16* __restrict__ Cl1,
              __nv_bfloat16* __restrict__ Ch2, __nv_bfloat16* __restrict__ Cl2,
              int M, int N, int K, int outN, int epi, int fused)
{
    extern __shared__ char smem[];
    const uint32_t s0 = (smem_u32(smem) + 1023) & ~1023u;

    const int tid = threadIdx.x;
    const int wid = tid >> 5, lid = tid & 31;
    const int brow = blockIdx.y << 7, bcol = blockIdx.x << 7;
    const int mw = (wid & 3) << 5;
    const int nw = (wid >> 2) << 6;

    // loader: 2 threads per row, each 4x 16B (64B half-row)
    const int lrow  = tid >> 1;
    const int lhalf = tid & 1;
    uint32_t sw[4];
#pragma unroll
    for (int i = 0; i < 4; i++)
        sw[i] = swz128(lrow * 128 + lhalf * 64 + i * 16);
    const size_t ga = (size_t)(brow + lrow) * K + lhalf * 32;
    const size_t gb = (size_t)(bcol + lrow) * K + lhalf * 32;

    const int nchunk = K >> 6;

    auto issue = [&](int c) {
        const uint32_t st = s0 + (uint32_t)(c % 3) * GSTAGEB;
        const size_t k0 = (size_t)c << 6;
#pragma unroll
        for (int i = 0; i < 4; i++) {
            cpasync16(st + 0 * GTILEB + sw[i], Ah + ga + k0 + i * 8);
            cpasync16(st + 1 * GTILEB + sw[i], Al + ga + k0 + i * 8);
            cpasync16(st + 2 * GTILEB + sw[i], Bh + gb + k0 + i * 8);
            cpasync16(st + 3 * GTILEB + sw[i], Bl + gb + k0 + i * 8);
        }
    };

    issue(0);
    asm volatile("cp.async.commit_group;");
    issue(1);
    asm volatile("cp.async.commit_group;");

    float acc[2][8][4];
#pragma unroll
    for (int i = 0; i < 2; i++)
#pragma unroll
        for (int j = 0; j < 8; j++)
#pragma unroll
            for (int t = 0; t < 4; t++) acc[i][j][t] = 0.f;

    const int a_row = lid & 15;
    const int a_h   = (lid >> 4) * 16;
    const int b_row = (lid & 7) + ((lid >> 4) << 3);
    const int b_h   = ((lid >> 3) & 1) * 16;

    for (int c = 0; c < nchunk; c++) {
        asm volatile("cp.async.wait_group 1;");
        __syncthreads();
        if (c + 2 < nchunk) issue(c + 2);
        asm volatile("cp.async.commit_group;");

        const uint32_t st  = s0 + (uint32_t)(c % 3) * GSTAGEB;
        const uint32_t sAh = st, sAl = st + GTILEB;
        const uint32_t sBh = st + 2 * GTILEB, sBl = st + 3 * GTILEB;

#pragma unroll
        for (int ks = 0; ks < 4; ks++) {
            uint32_t ah[2][4], al[2][4];
#pragma unroll
            for (int i = 0; i < 2; i++) {
                uint32_t off = swz128((mw + i * 16 + a_row) * 128 + ks * 32 + a_h);
                ldsm4(ah[i], sAh + off);
                ldsm4(al[i], sAl + off);
            }
            uint32_t bh[8][2], bl[8][2];
#pragma unroll
            for (int jj = 0; jj < 4; jj++) {
                uint32_t off = swz128((nw + jj * 16 + b_row) * 128 + ks * 32 + b_h);
                uint32_t t0[4], t1[4];
                ldsm4(t0, sBh + off);
                ldsm4(t1, sBl + off);
                bh[2*jj][0] = t0[0]; bh[2*jj][1] = t0[1]; bh[2*jj+1][0] = t0[2]; bh[2*jj+1][1] = t0[3];
                bl[2*jj][0] = t1[0]; bl[2*jj][1] = t1[1]; bl[2*jj+1][0] = t1[2]; bl[2*jj+1][1] = t1[3];
            }
#pragma unroll
            for (int i = 0; i < 2; i++)
#pragma unroll
                for (int j = 0; j < 8; j++) {
                    mma16816(acc[i][j], ah[i], bh[j][0], bh[j][1]);
                    mma16816(acc[i][j], ah[i], bl[j][0], bl[j][1]);
                    mma16816(acc[i][j], al[i], bh[j][0], bh[j][1]);
                }
        }
    }

    // ---- epilogue ----
    int sel = fused ? (bcol >> 10) : 0;
    const int nbase = fused ? (bcol & 1023) : bcol;
    __nv_bfloat16* Ch = (sel == 0) ? Ch0 : (sel == 1) ? Ch1 : Ch2;
    __nv_bfloat16* Cl = (sel == 0) ? Cl0 : (sel == 1) ? Cl1 : Cl2;

    const int erow = lid >> 2;
    const int ecol = (lid & 3) << 1;
#pragma unroll
    for (int i = 0; i < 2; i++)
#pragma unroll
        for (int j = 0; j < 8; j++)
#pragma unroll
            for (int h = 0; h < 2; h++) {
                const int m = brow + mw + i * 16 + erow + h * 8;
                const int ng = bcol + nw + j * 8 + ecol;             // global (bias)
                const int nl = nbase + nw + j * 8 + ecol;            // local (store)
                float v0 = acc[i][j][h * 2 + 0] + bias[ng];
                float v1 = acc[i][j][h * 2 + 1] + bias[ng + 1];
                const size_t off = (size_t)m * outN + nl;
                if (epi == 1) {
                    v0 = 0.5f * v0 * (1.0f + erff(v0 * 0.70710678118654752f));
                    v1 = 0.5f * v1 * (1.0f + erff(v1 * 0.70710678118654752f));
                } else if (epi == 2) {
                    float2 rr = *(const float2*)&res[off];
                    v0 += rr.x; v1 += rr.y;
                }
                if (Cf) *(float2*)&Cf[off] = make_float2(v0, v1);
                if (Ch) {
                    uint32_t hh, ll;
                    split_pack2(v0, v1, hh, ll);
                    *(uint32_t*)&Ch[off] = hh;
                    *(uint32_t*)&Cl[off] = ll;
                }
            }
}

// =====================================================================
// Causal flash attention via HMMA bf16 hi/lo split. fp32 softmax.
// =====================================================================
#define ATT_STAGEB 32768
#define SMEM_ATT (1024 + 32768 + 3 * ATT_STAGEB)

__global__ __launch_bounds__(256, 1)
void attn_mma(const __nv_bfloat16* __restrict__ Qh, const __nv_bfloat16* __restrict__ Ql,
              const __nv_bfloat16* __restrict__ Kh, const __nv_bfloat16* __restrict__ Kl,
              const __nv_bfloat16* __restrict__ Vh, const __nv_bfloat16* __restrict__ Vl,
              __nv_bfloat16* __restrict__ Oh, __nv_bfloat16* __restrict__ Ol)
{
    extern __shared__ char sm[];
    const uint32_t sQh = (smem_u32(sm) + 1023) & ~1023u;
    const uint32_t sQl = sQh + 16384;
    const uint32_t sKV = sQh + 32768;

    const int tid = threadIdx.x, wid = tid >> 5, lid = tid & 31;
    const int qt = (int)gridDim.x - 1 - (int)blockIdx.x;
    const int bh = blockIdx.y;
    const int b = bh >> 4, h = bh & 15;
    const int qbase = qt * 128;
    const size_t tok0 = (size_t)b * SEQ;
    const size_t hoff = (size_t)h * 64;
    const int mw = wid * 16;

    {
        const int r = tid >> 1;
        const int half = tid & 1;
        const size_t g = (tok0 + qbase + r) * DM + hoff + half * 32;
#pragma unroll
        for (int i = 0; i < 4; i++) {
            uint32_t so = swz128(r * 128 + half * 64 + i * 16);
            cpasync16(sQh + so, Qh + g + i * 8);
            cpasync16(sQl + so, Ql + g + i * 8);
        }
    }

    const int njt = 2 * qt + 2;
    const int kr = tid >> 2;
    const int kq = tid & 3;
    const uint32_t kso0 = swz128(kr * 128 + kq * 32);
    const uint32_t kso1 = swz128(kr * 128 + kq * 32 + 16);

    auto issue_kv = [&](int jt) {
        const uint32_t st = sKV + (uint32_t)(jt % 3) * ATT_STAGEB;
        const size_t g = (tok0 + jt * 64 + kr) * DM + hoff + kq * 16;
        cpasync16(st +         kso0, Kh + g);
        cpasync16(st +         kso1, Kh + g + 8);
        cpasync16(st +  8192 + kso0, Kl + g);
        cpasync16(st +  8192 + kso1, Kl + g + 8);
        cpasync16(st + 16384 + kso0, Vh + g);
        cpasync16(st + 16384 + kso1, Vh + g + 8);
        cpasync16(st + 24576 + kso0, Vl + g);
        cpasync16(st + 24576 + kso1, Vl + g + 8);
    };

    issue_kv(0);
    asm volatile("cp.async.commit_group;");
    issue_kv(1);
    asm volatile("cp.async.commit_group;");

    float O[8][4];
#pragma unroll
    for (int j = 0; j < 8; j++)
#pragma unroll
        for (int e = 0; e < 4; e++) O[j][e] = 0.f;
    float m0 = -1e30f, m1 = -1e30f, l0 = 0.f, l1 = 0.f;

    const int rql = lid >> 2;
    const int cql = (lid & 3) * 2;
    const int row0g = qbase + mw + rql;
    const int row1g = row0g + 8;

    for (int jt = 0; jt < njt; jt++) {
        asm volatile("cp.async.wait_group 1;");
        __syncthreads();
        if (jt + 2 < njt) issue_kv(jt + 2);
        asm volatile("cp.async.commit_group;");

        const bool active = !(mw < 64 && jt == njt - 1);
        if (active) {
            const uint32_t stKh = sKV + (uint32_t)(jt % 3) * ATT_STAGEB;
            const uint32_t stKl = stKh + 8192;
            const uint32_t stVh = stKh + 16384, stVl = stKh + 24576;

            float S[8][4];
#pragma unroll
            for (int j = 0; j < 8; j++)
#pragma unroll
                for (int e = 0; e < 4; e++) S[j][e] = 0.f;

#pragma unroll
            for (int ks = 0; ks < 4; ks++) {
                uint32_t qh4[4], ql4[4];
                uint32_t qoff = swz128((mw + (lid & 15)) * 128 + ks * 32 + (lid >> 4) * 16);
                ldsm4(qh4, sQh + qoff);
                ldsm4(ql4, sQl + qoff);
                uint32_t kfh[8][2], kfl[8][2];
#pragma unroll
                for (int jj = 0; jj < 4; jj++) {
                    uint32_t koff = swz128((jj * 16 + (lid & 7) + ((lid >> 4) << 3)) * 128
                                           + ks * 32 + ((lid >> 3) & 1) * 16);
                    uint32_t t0[4], t1[4];
                    ldsm4(t0, stKh + koff);
                    ldsm4(t1, stKl + koff);
                    kfh[2*jj][0]=t0[0]; kfh[2*jj][1]=t0[1]; kfh[2*jj+1][0]=t0[2]; kfh[2*jj+1][1]=t0[3];
                    kfl[2*jj][0]=t1[0]; kfl[2*jj][1]=t1[1]; kfl[2*jj+1][0]=t1[2]; kfl[2*jj+1][1]=t1[3];
                }
#pragma unroll
                for (int j = 0; j < 8; j++) mma16816(S[j], qh4, kfh[j][0], kfh[j][1]);
#pragma unroll
                for (int j = 0; j < 8; j++) mma16816(S[j], qh4, kfl[j][0], kfl[j][1]);
#pragma unroll
                for (int j = 0; j < 8; j++) mma16816(S[j], ql4, kfh[j][0], kfh[j][1]);
            }

            const int colb = jt * 64;
            const bool diag = (jt >= 2 * qt);
#pragma unroll
            for (int j = 0; j < 8; j++)
#pragma unroll
                for (int e = 0; e < 4; e++) {
                    float v = S[j][e] * 0.125f;
                    if (diag) {
                        int col = colb + 8 * j + cql + (e & 1);
                        int row = (e < 2) ? row0g : row1g;
                        if (col > row) v = -1e30f;
                    }
                    S[j][e] = v;
                }

            float rm0 = -1e30f, rm1 = -1e30f;
#pragma unroll
            for (int j = 0; j < 8; j++) {
                rm0 = fmaxf(rm0, fmaxf(S[j][0], S[j][1]));
                rm1 = fmaxf(rm1, fmaxf(S[j][2], S[j][3]));
            }
            rm0 = fmaxf(rm0, __shfl_xor_sync(0xffffffffu, rm0, 1));
            rm0 = fmaxf(rm0, __shfl_xor_sync(0xffffffffu, rm0, 2));
            rm1 = fmaxf(rm1, __shfl_xor_sync(0xffffffffu, rm1, 1));
            rm1 = fmaxf(rm1, __shfl_xor_sync(0xffffffffu, rm1, 2));
            float mn0 = fmaxf(m0, rm0), mn1 = fmaxf(m1, rm1);
            float a0 = __expf(m0 - mn0), a1 = __expf(m1 - mn1);
            m0 = mn0; m1 = mn1;
            float rs0 = 0.f, rs1 = 0.f;
#pragma unroll
            for (int j = 0; j < 8; j++) {
                S[j][0] = __expf(S[j][0] - mn0);
                S[j][1] = __expf(S[j][1] - mn0);
                S[j][2] = __expf(S[j][2] - mn1);
                S[j][3] = __expf(S[j][3] - mn1);
                rs0 += S[j][0] + S[j][1];
                rs1 += S[j][2] + S[j][3];
            }
            rs0 += __shfl_xor_sync(0xffffffffu, rs0, 1);
            rs0 += __shfl_xor_sync(0xffffffffu, rs0, 2);
            rs1 += __shfl_xor_sync(0xffffffffu, rs1, 1);
            rs1 += __shfl_xor_sync(0xffffffffu, rs1, 2);
            l0 = l0 * a0 + rs0;
            l1 = l1 * a1 + rs1;
#pragma unroll
            for (int j = 0; j < 8; j++) {
                O[j][0] *= a0; O[j][1] *= a0; O[j][2] *= a1; O[j][3] *= a1;
            }

            uint32_t pah[4][4], pal[4][4];
#pragma unroll
            for (int ks = 0; ks < 4; ks++) {
                split_pack2(S[2*ks][0],   S[2*ks][1],   pah[ks][0], pal[ks][0]);
                split_pack2(S[2*ks][2],   S[2*ks][3],   pah[ks][1], pal[ks][1]);
                split_pack2(S[2*ks+1][0], S[2*ks+1][1], pah[ks][2], pal[ks][2]);
                split_pack2(S[2*ks+1][2], S[2*ks+1][3], pah[ks][3], pal[ks][3]);
            }

#pragma unroll
            for (int ks = 0; ks < 4; ks++) {
                uint32_t vfh[8][2], vfl[8][2];
                const int rowv = ks * 16 + ((lid >> 3) & 1) * 8 + (lid & 7);
                const int colv = (lid >> 4) * 16;
#pragma unroll
                for (int nb = 0; nb < 4; nb++) {
                    uint32_t voff = swz128(rowv * 128 + nb * 32 + colv);
                    uint32_t t0[4], t1[4];
                    ldsm4t(t0, stVh + voff);
                    ldsm4t(t1, stVl + voff);
                    vfh[2*nb][0]=t0[0]; vfh[2*nb][1]=t0[1]; vfh[2*nb+1][0]=t0[2]; vfh[2*nb+1][1]=t0[3];
                    vfl[2*nb][0]=t1[0]; vfl[2*nb][1]=t1[1]; vfl[2*nb+1][0]=t1[2]; vfl[2*nb+1][1]=t1[3];
                }
#pragma unroll
                for (int j = 0; j < 8; j++) mma16816(O[j], pah[ks], vfh[j][0], vfh[j][1]);
#pragma unroll
                for (int j = 0; j < 8; j++) mma16816(O[j], pah[ks], vfl[j][0], vfl[j][1]);
#pragma unroll
                for (int j = 0; j < 8; j++) mma16816(O[j], pal[ks], vfh[j][0], vfh[j][1]);
            }
        }
    }

    const float inv0 = 1.0f / l0, inv1 = 1.0f / l1;
    const size_t tq0 = (tok0 + row0g) * DM + hoff;
    const size_t tq1 = (tok0 + row1g) * DM + hoff;
#pragma unroll
    for (int j = 0; j < 8; j++) {
        const int c = 8 * j + cql;
        uint32_t hh, ll;
        split_pack2(O[j][0] * inv0, O[j][1] * inv0, hh, ll);
        *(uint32_t*)&Oh[tq0 + c] = hh;
        *(uint32_t*)&Ol[tq0 + c] = ll;
        split_pack2(O[j][2] * inv1, O[j][3] * inv1, hh, ll);
        *(uint32_t*)&Oh[tq1 + c] = hh;
        *(uint32_t*)&Ol[tq1 + c] = ll;
    }
}

// =====================================================================
// conversions
// =====================================================================
__device__ __forceinline__ void split_bf16(float v, __nv_bfloat16& h, __nv_bfloat16& l) {
    h = __float2bfloat16(v);
    l = __float2bfloat16(v - __bfloat162float(h));
}

__global__ __launch_bounds__(256)
void conv_act(const float* __restrict__ in, __nv_bfloat16* __restrict__ hi,
              __nv_bfloat16* __restrict__ lo)
{
    const size_t i = ((size_t)blockIdx.x * 256 + threadIdx.x) * 4;
    float4 v = *(const float4*)(in + i);
    uint32_t h0, l0, h1, l1;
    split_pack2(v.x, v.y, h0, l0);
    split_pack2(v.z, v.w, h1, l1);
    *(uint32_t*)&hi[i]     = h0;
    *(uint32_t*)&hi[i + 2] = h1;
    *(uint32_t*)&lo[i]     = l0;
    *(uint32_t*)&lo[i + 2] = l1;
}

// transpose W[K,N] -> hi/lo [N,K]  (single weight)
__global__ __launch_bounds__(256)
void conv_wT(const float* __restrict__ W, __nv_bfloat16* __restrict__ hi,
             __nv_bfloat16* __restrict__ lo, int K, int N)
{
    __shared__ float t[32][33];
    const int n0 = blockIdx.x * 32, k0 = blockIdx.y * 32;
    const int tx = threadIdx.x & 31, ty = threadIdx.x >> 5;
#pragma unroll
    for (int j = 0; j < 4; j++)
        t[ty + 8 * j][tx] = W[(size_t)(k0 + ty + 8 * j) * N + n0 + tx];
    __syncthreads();
#pragma unroll
    for (int j = 0; j < 4; j++) {
        float v = t[tx][ty + 8 * j];
        __nv_bfloat16 h, l;
        split_bf16(v, h, l);
        size_t o = (size_t)(n0 + ty + 8 * j) * K + k0 + tx;
        hi[o] = h; lo[o] = l;
    }
}

// fused QKV weight transpose: Wq/Wk/Wv [1024,1024] -> wqkv [3072,1024] hi/lo
__global__ __launch_bounds__(256)
void conv_wT3(const float* __restrict__ W0, const float* __restrict__ W1,
              const float* __restrict__ W2, __nv_bfloat16* __restrict__ hi,
              __nv_bfloat16* __restrict__ lo)
{
    __shared__ float t[32][33];
    const int n0 = blockIdx.x * 32, k0 = blockIdx.y * 32;
    const int sel = n0 >> 10;
    const int nl = n0 & 1023;
    const float* W = (sel == 0) ? W0 : (sel == 1) ? W1 : W2;
    const int tx = threadIdx.x & 31, ty = threadIdx.x >> 5;
#pragma unroll
    for (int j = 0; j < 4; j++)
        t[ty + 8 * j][tx] = W[(size_t)(k0 + ty + 8 * j) * 1024 + nl + tx];
    __syncthreads();
#pragma unroll
    for (int j = 0; j < 4; j++) {
        float v = t[tx][ty + 8 * j];
        __nv_bfloat16 h, l;
        split_bf16(v, h, l);
        size_t o = (size_t)(n0 + ty + 8 * j) * 1024 + k0 + tx;
        hi[o] = h; lo[o] = l;
    }
}

__global__ void bias_cat(const float* __restrict__ b0, const float* __restrict__ b1,
                         const float* __restrict__ b2, float* __restrict__ out)
{
    int i = blockIdx.x * 256 + threadIdx.x;
    out[i] = (i < 1024) ? b0[i] : (i < 2048) ? b1[i - 1024] : b2[i - 2048];
}

// =====================================================================
// LayerNorm (+ optional bf16 hi/lo split out)
// =====================================================================
__global__ __launch_bounds__(256)
void ln_kernel(const float* __restrict__ in, const float* __restrict__ gamma,
               const float* __restrict__ beta, float* __restrict__ out,
               __nv_bfloat16* __restrict__ oh, __nv_bfloat16* __restrict__ ol)
{
    __shared__ float rs[8], rs2[8];
    const int row = blockIdx.x;
    const int t = threadIdx.x;
    float4 v = ((const float4*)(in + (size_t)row * DM))[t];
    float s  = v.x + v.y + v.z + v.w;
    float s2 = v.x * v.x + v.y * v.y + v.z * v.z + v.w * v.w;
#pragma unroll
    for (int off = 16; off; off >>= 1) {
        s  += __shfl_xor_sync(0xffffffffu, s, off);
        s2 += __shfl_xor_sync(0xffffffffu, s2, off);
    }
    if ((t & 31) == 0) { rs[t >> 5] = s; rs2[t >> 5] = s2; }
    __syncthreads();
    float ts = 0.f, ts2 = 0.f;
#pragma unroll
    for (int w = 0; w < 8; w++) { ts += rs[w]; ts2 += rs2[w]; }
    float mu   = ts * (1.0f / DM);
    float var  = ts2 * (1.0f / DM) - mu * mu;
    float rstd = rsqrtf(var + 1e-5f);
    float4 g4 = ((const float4*)gamma)[t];
    float4 b4 = ((const float4*)beta)[t];
    float4 o4;
    o4.x = (v.x - mu) * rstd * g4.x + b4.x;
    o4.y = (v.y - mu) * rstd * g4.y + b4.y;
    o4.z = (v.z - mu) * rstd * g4.z + b4.z;
    o4.w = (v.w - mu) * rstd * g4.w + b4.w;
    ((float4*)(out + (size_t)row * DM))[t] = o4;
    if (oh) {
        const size_t i = (size_t)row * DM + t * 4;
        uint32_t h0, l0, h1, l1;
        split_pack2(o4.x, o4.y, h0, l0);
        split_pack2(o4.z, o4.w, h1, l1);
        *(uint32_t*)&oh[i]     = h0;
        *(uint32_t*)&oh[i + 2] = h1;
        *(uint32_t*)&ol[i]     = l0;
        *(uint32_t*)&ol[i + 2] = l1;
    }
}

// =====================================================================
extern "C" void kernel_launch(void* const* d_in, const int* in_sizes, int n_in,
                              void* d_out, int out_size)
{
    (void)in_sizes; (void)n_in; (void)out_size;
    const float* x   = (const float*)d_in[0];
    const float* Wq  = (const float*)d_in[1];
    const float* bq  = (const float*)d_in[2];
    const float* Wk  = (const float*)d_in[3];
    const float* bk  = (const float*)d_in[4];
    const float* Wv  = (const float*)d_in[5];
    const float* bv  = (const float*)d_in[6];
    const float* Wo  = (const float*)d_in[7];
    const float* bo  = (const float*)d_in[8];
    const float* W1  = (const float*)d_in[9];
    const float* b1  = (const float*)d_in[10];
    const float* W2  = (const float*)d_in[11];
    const float* b2  = (const float*)d_in[12];
    const float* g1  = (const float*)d_in[13];
    const float* be1 = (const float*)d_in[14];
    const float* g2  = (const float*)d_in[15];
    const float* be2 = (const float*)d_in[16];
    float* out = (float*)d_out;

    float *gt0, *gx1, *gbqkv;
    cudaGetSymbolAddress((void**)&gt0, g_t0);
    cudaGetSymbolAddress((void**)&gx1, g_x1);
    cudaGetSymbolAddress((void**)&gbqkv, g_bqkv);

    __nv_bfloat16 *xh, *xl, *qh, *ql, *kh, *kl, *vh, *vl, *ctxh, *ctxl, *x1h, *x1l, *ffh, *ffl;
    __nv_bfloat16 *wqkvh, *wqkvl, *woh, *wol, *w1h, *w1l, *w2h, *w2l;
    cudaGetSymbolAddress((void**)&xh,    g_xh);    cudaGetSymbolAddress((void**)&xl,    g_xl);
    cudaGetSymbolAddress((void**)&qh,    g_qh);    cudaGetSymbolAddress((void**)&ql,    g_ql);
    cudaGetSymbolAddress((void**)&kh,    g_kh);    cudaGetSymbolAddress((void**)&kl,    g_kl);
    cudaGetSymbolAddress((void**)&vh,    g_vh);    cudaGetSymbolAddress((void**)&vl,    g_vl);
    cudaGetSymbolAddress((void**)&ctxh,  g_ctxh);  cudaGetSymbolAddress((void**)&ctxl,  g_ctxl);
    cudaGetSymbolAddress((void**)&x1h,   g_x1h);   cudaGetSymbolAddress((void**)&x1l,   g_x1l);
    cudaGetSymbolAddress((void**)&ffh,   g_ffh);   cudaGetSymbolAddress((void**)&ffl,   g_ffl);
    cudaGetSymbolAddress((void**)&wqkvh, g_wqkvh); cudaGetSymbolAddress((void**)&wqkvl, g_wqkvl);
    cudaGetSymbolAddress((void**)&woh,   g_woh);   cudaGetSymbolAddress((void**)&wol,   g_wol);
    cudaGetSymbolAddress((void**)&w1h,   g_w1h);   cudaGetSymbolAddress((void**)&w1l,   g_w1l);
    cudaGetSymbolAddress((void**)&w2h,   g_w2h);   cudaGetSymbolAddress((void**)&w2l,   g_w2l);

    cudaFuncSetAttribute(mma_gemm, cudaFuncAttributeMaxDynamicSharedMemorySize, SMEM_MMA);
    cudaFuncSetAttribute(attn_mma, cudaFuncAttributeMaxDynamicSharedMemorySize, SMEM_ATT);

    // ---- weight prep ----
    conv_wT3<<<dim3(3 * DM / 32, DM / 32), 256>>>(Wq, Wk, Wv, wqkvh, wqkvl);
    conv_wT<<<dim3(DM / 32,  DM / 32),  256>>>(Wo, woh, wol, DM, DM);
    conv_wT<<<dim3(DFF / 32, DM / 32),  256>>>(W1, w1h, w1l, DM, DFF);
    conv_wT<<<dim3(DM / 32,  DFF / 32), 256>>>(W2, w2h, w2l, DFF, DM);
    bias_cat<<<12, 256>>>(bq, bk, bv, gbqkv);

    // ---- x split ----
    conv_act<<<(NTOK * DM) / 1024, 256>>>(x, xh, xl);

    // ---- fused QKV GEMM (N=3072) ----
    mma_gemm<<<dim3(3 * DM / 128, NTOK / 128), 256, SMEM_MMA>>>(
        xh, xl, wqkvh, wqkvl, gbqkv, nullptr, nullptr,
        qh, ql, kh, kl, vh, vl, NTOK, 3 * DM, DM, DM, 0, 1);

    // ---- attention ----
    attn_mma<<<dim3(SEQ / 128, 32), 256, SMEM_ATT>>>(qh, ql, kh, kl, vh, vl, ctxh, ctxl);

    // ---- Wo + residual, LN1 (+split) ----
    mma_gemm<<<dim3(DM / 128, NTOK / 128), 256, SMEM_MMA>>>(
        ctxh, ctxl, woh, wol, bo, x, gt0,
        nullptr, nullptr, nullptr, nullptr, nullptr, nullptr, NTOK, DM, DM, DM, 2, 0);
    ln_kernel<<<NTOK, 256>>>(gt0, g1, be1, gx1, x1h, x1l);

    // ---- FFN ----
    mma_gemm<<<dim3(DFF / 128, NTOK / 128), 256, SMEM_MMA>>>(
        x1h, x1l, w1h, w1l, b1, nullptr, nullptr,
        ffh, ffl, nullptr, nullptr, nullptr, nullptr, NTOK, DFF, DM, DFF, 1, 0);
    mma_gemm<<<dim3(DM / 128, NTOK / 128), 256, SMEM_MMA>>>(
        ffh, ffl, w2h, w2l, b2, gx1, gt0,
        nullptr, nullptr, nullptr, nullptr, nullptr, nullptr, NTOK, DM, DFF, DM, 2, 0);
    ln_kernel<<<NTOK, 256>>>(gt0, g2, be2, out, nullptr, nullptr);
}